// round 1
// baseline (speedup 1.0000x reference)
#include <cuda_runtime.h>
#include <math.h>

#define BATCH 2
#define SEQ 2048
#define DM 1024
#define NH 16
#define HD 64
#define EPSV 1e-6f

// Scratch buffers (allocation-free rule: __device__ globals)
__device__ float g_q[BATCH * SEQ * DM];
__device__ float g_k[BATCH * SEQ * DM];
__device__ float g_v[BATCH * SEQ * DM];
__device__ float g_attn[BATCH * SEQ * DM];

// ---------------------------------------------------------------------------
// C[m,n] = sum_k A[m,k] * W[n,k]   (NT GEMM, both K-contiguous)
// 64x64 tile, BK=16, 256 threads, 4x4 microtile per thread.
// ---------------------------------------------------------------------------
__global__ void gemm_nt(const float* __restrict__ A, const float* __restrict__ W,
                        float* __restrict__ C, int M, int N, int K)
{
    __shared__ float As[64][17];
    __shared__ float Ws[64][17];
    int tid = threadIdx.x;
    int ty = tid >> 4, tx = tid & 15;
    int bm = blockIdx.y * 64, bn = blockIdx.x * 64;

    float acc[4][4];
#pragma unroll
    for (int i = 0; i < 4; i++)
#pragma unroll
        for (int j = 0; j < 4; j++) acc[i][j] = 0.f;

    for (int k0 = 0; k0 < K; k0 += 16) {
#pragma unroll
        for (int i = 0; i < 4; i++) {
            int idx = tid + i * 256;
            int r = idx >> 4, c = idx & 15;
            As[r][c] = A[(size_t)(bm + r) * K + k0 + c];
            Ws[r][c] = W[(size_t)(bn + r) * K + k0 + c];
        }
        __syncthreads();
#pragma unroll
        for (int kk = 0; kk < 16; kk++) {
            float a[4], b[4];
#pragma unroll
            for (int i = 0; i < 4; i++) a[i] = As[ty * 4 + i][kk];
#pragma unroll
            for (int j = 0; j < 4; j++) b[j] = Ws[tx * 4 + j][kk];
#pragma unroll
            for (int i = 0; i < 4; i++)
#pragma unroll
                for (int j = 0; j < 4; j++)
                    acc[i][j] += a[i] * b[j];
        }
        __syncthreads();
    }
#pragma unroll
    for (int i = 0; i < 4; i++)
#pragma unroll
        for (int j = 0; j < 4; j++)
            C[(size_t)(bm + ty * 4 + i) * N + bn + tx * 4 + j] = acc[i][j];
}

// ---------------------------------------------------------------------------
// RMSNorm (over HD=64) + interleaved RoPE. One warp per (b, s, h) row.
// Lane i holds the float2 pair (2i, 2i+1) == RoPE pair with freq index i.
// ---------------------------------------------------------------------------
__global__ void norm_rope(float* __restrict__ t, const float* __restrict__ scale,
                          const float* __restrict__ cosT, const float* __restrict__ sinT)
{
    int warp = (blockIdx.x * blockDim.x + threadIdx.x) >> 5;
    int lane = threadIdx.x & 31;

    float2* row = reinterpret_cast<float2*>(t + (size_t)warp * 64);
    float2 v = row[lane];

    float ss = v.x * v.x + v.y * v.y;
#pragma unroll
    for (int m = 16; m >= 1; m >>= 1) ss += __shfl_xor_sync(0xffffffffu, ss, m);
    float r = rsqrtf(ss * (1.0f / 64.0f) + EPSV);

    int s = (warp / NH) & (SEQ - 1);
    float c  = cosT[s * (HD / 2) + lane];
    float sn = sinT[s * (HD / 2) + lane];

    float tr = v.x * r * scale[2 * lane];
    float ti = v.y * r * scale[2 * lane + 1];
    float2 o;
    o.x = tr * c - ti * sn;
    o.y = tr * sn + ti * c;
    row[lane] = o;
}

// ---------------------------------------------------------------------------
// Flash attention (non-causal, full softmax over S).
// Grid: (S/64, H, B). Block: 256 threads (16x16 logical).
// Q tile 64 rows; K/V tiles of 32 rows. fp32 throughout.
// ---------------------------------------------------------------------------
__global__ void attn_kernel(const float* __restrict__ Q, const float* __restrict__ K,
                            const float* __restrict__ V, float* __restrict__ O)
{
    __shared__ float Qs[64][65];
    __shared__ float Ks[32][65];
    __shared__ float Vs[32][65];
    __shared__ float Ps[64][33];

    int tid = threadIdx.x;
    int ty = tid >> 4, tx = tid & 15;
    int b = blockIdx.z, h = blockIdx.y;
    int q0 = blockIdx.x * 64;
    const float softscale = 0.125f; // 1/sqrt(64)

    for (int i = tid; i < 64 * 64; i += 256) {
        int r = i >> 6, d = i & 63;
        Qs[r][d] = Q[((size_t)(b * SEQ + q0 + r)) * DM + h * HD + d] * softscale;
    }

    float m_i[4], l_i[4], o_acc[4][4];
#pragma unroll
    for (int i = 0; i < 4; i++) {
        m_i[i] = -INFINITY; l_i[i] = 0.f;
#pragma unroll
        for (int j = 0; j < 4; j++) o_acc[i][j] = 0.f;
    }
    __syncthreads();

    for (int kt = 0; kt < SEQ; kt += 32) {
        for (int i = tid; i < 32 * 64; i += 256) {
            int r = i >> 6, d = i & 63;
            size_t g = ((size_t)(b * SEQ + kt + r)) * DM + h * HD + d;
            Ks[r][d] = K[g];
            Vs[r][d] = V[g];
        }
        __syncthreads();

        // scores: rows ty*4+i (q), cols tx*2+j (k)
        float sc[4][2];
#pragma unroll
        for (int i = 0; i < 4; i++) { sc[i][0] = 0.f; sc[i][1] = 0.f; }
#pragma unroll
        for (int kk = 0; kk < 64; kk++) {
            float a[4], bb[2];
#pragma unroll
            for (int i = 0; i < 4; i++) a[i] = Qs[ty * 4 + i][kk];
#pragma unroll
            for (int j = 0; j < 2; j++) bb[j] = Ks[tx * 2 + j][kk];
#pragma unroll
            for (int i = 0; i < 4; i++) {
                sc[i][0] += a[i] * bb[0];
                sc[i][1] += a[i] * bb[1];
            }
        }

        // online softmax update (16-lane tx-group reductions; shfl masks
        // 1..8 only flip the low 4 lane bits, staying inside each group)
#pragma unroll
        for (int i = 0; i < 4; i++) {
            float mx = fmaxf(sc[i][0], sc[i][1]);
#pragma unroll
            for (int mk = 8; mk >= 1; mk >>= 1)
                mx = fmaxf(mx, __shfl_xor_sync(0xffffffffu, mx, mk));
            float mn = fmaxf(m_i[i], mx);
            float alpha = __expf(m_i[i] - mn);
            m_i[i] = mn;
            float p0 = __expf(sc[i][0] - mn);
            float p1 = __expf(sc[i][1] - mn);
            float rs = p0 + p1;
#pragma unroll
            for (int mk = 8; mk >= 1; mk >>= 1)
                rs += __shfl_xor_sync(0xffffffffu, rs, mk);
            l_i[i] = l_i[i] * alpha + rs;
            Ps[ty * 4 + i][tx * 2 + 0] = p0;
            Ps[ty * 4 + i][tx * 2 + 1] = p1;
#pragma unroll
            for (int j = 0; j < 4; j++) o_acc[i][j] *= alpha;
        }
        __syncthreads();

        // O += P @ V  (O cols = HD cols, tx*4..tx*4+3)
#pragma unroll
        for (int kk = 0; kk < 32; kk++) {
            float a[4], bb[4];
#pragma unroll
            for (int i = 0; i < 4; i++) a[i] = Ps[ty * 4 + i][kk];
#pragma unroll
            for (int j = 0; j < 4; j++) bb[j] = Vs[kk][tx * 4 + j];
#pragma unroll
            for (int i = 0; i < 4; i++)
#pragma unroll
                for (int j = 0; j < 4; j++)
                    o_acc[i][j] += a[i] * bb[j];
        }
        __syncthreads();
    }

#pragma unroll
    for (int i = 0; i < 4; i++) {
        float inv = 1.0f / l_i[i];
#pragma unroll
        for (int j = 0; j < 4; j++)
            O[((size_t)(b * SEQ + q0 + ty * 4 + i)) * DM + h * HD + tx * 4 + j] =
                o_acc[i][j] * inv;
    }
}

// ---------------------------------------------------------------------------
extern "C" void kernel_launch(void* const* d_in, const int* in_sizes, int n_in,
                              void* d_out, int out_size)
{
    const float* x        = (const float*)d_in[0];
    const float* wq       = (const float*)d_in[1];
    const float* wk       = (const float*)d_in[2];
    const float* wv       = (const float*)d_in[3];
    const float* wo       = (const float*)d_in[4];
    const float* q_scale  = (const float*)d_in[5];
    const float* k_scale  = (const float*)d_in[6];
    const float* rope_cos = (const float*)d_in[7];
    const float* rope_sin = (const float*)d_in[8];
    float* out = (float*)d_out;

    float *q, *k, *v, *attn;
    cudaGetSymbolAddress((void**)&q, g_q);
    cudaGetSymbolAddress((void**)&k, g_k);
    cudaGetSymbolAddress((void**)&v, g_v);
    cudaGetSymbolAddress((void**)&attn, g_attn);

    const int M = BATCH * SEQ;      // 4096
    dim3 ggrid(DM / 64, M / 64);    // (16, 64)

    gemm_nt<<<ggrid, 256>>>(x, wq, q, M, DM, DM);
    gemm_nt<<<ggrid, 256>>>(x, wk, k, M, DM, DM);
    gemm_nt<<<ggrid, 256>>>(x, wv, v, M, DM, DM);

    int nwarps = BATCH * SEQ * NH;          // 65536
    int nblocks = nwarps / 8;               // 8 warps per 256-thread block
    norm_rope<<<nblocks, 256>>>(q, q_scale, rope_cos, rope_sin);
    norm_rope<<<nblocks, 256>>>(k, k_scale, rope_cos, rope_sin);

    dim3 agrid(SEQ / 64, NH, BATCH);        // (32, 16, 2)
    attn_kernel<<<agrid, 256>>>(q, k, v, attn);

    gemm_nt<<<ggrid, 256>>>(attn, wo, out, M, DM, DM);
}

// round 3
// speedup vs baseline: 2.5721x; 2.5721x over previous
#include <cuda_runtime.h>
#include <cuda_bf16.h>
#include <cstdint>
#include <math.h>

#define BATCH 2
#define SEQ 2048
#define DM 1024
#define NH 16
#define HD 64
#define EPSV 1e-6f

// ---------------------------------------------------------------------------
// Scratch (__device__ globals: allocation-free rule)
// ---------------------------------------------------------------------------
__device__ __nv_bfloat16 g_xh[BATCH * SEQ * DM];
__device__ __nv_bfloat16 g_xl[BATCH * SEQ * DM];
__device__ __nv_bfloat16 g_wqh[DM * DM], g_wql[DM * DM];
__device__ __nv_bfloat16 g_wkh[DM * DM], g_wkl[DM * DM];
__device__ __nv_bfloat16 g_wvh[DM * DM], g_wvl[DM * DM];
__device__ __nv_bfloat16 g_woh[DM * DM], g_wol[DM * DM];
__device__ float g_qf[BATCH * SEQ * DM];
__device__ float g_kf[BATCH * SEQ * DM];
__device__ float g_vf[BATCH * SEQ * DM];
__device__ __nv_bfloat16 g_qbh[BATCH * NH * SEQ * HD], g_qbl[BATCH * NH * SEQ * HD];
__device__ __nv_bfloat16 g_kbh[BATCH * NH * SEQ * HD], g_kbl[BATCH * NH * SEQ * HD];
__device__ __nv_bfloat16 g_vth[BATCH * NH * HD * SEQ], g_vtl[BATCH * NH * HD * SEQ];
__device__ float g_scores[(size_t)BATCH * NH * SEQ * SEQ];          // 512 MB
__device__ __nv_bfloat16 g_ph[(size_t)BATCH * NH * SEQ * SEQ];      // 256 MB
__device__ __nv_bfloat16 g_pl[(size_t)BATCH * NH * SEQ * SEQ];      // 256 MB
__device__ __nv_bfloat16 g_ath[BATCH * SEQ * DM], g_atl[BATCH * SEQ * DM];

// ---------------------------------------------------------------------------
// Helpers (all non-'a' instructions: legal under compute_103)
// ---------------------------------------------------------------------------
__device__ __forceinline__ uint32_t smem_to_u32(const void* p) {
    uint32_t a;
    asm("{ .reg .u64 t; cvta.to.shared.u64 t, %1; cvt.u32.u64 %0, t; }" : "=r"(a) : "l"(p));
    return a;
}
#define SMEM_SWIZZLE_128B(o) ((o) ^ (((o) >> 3) & 0x70))

#define CP_ASYNC16(dst, src) \
    asm volatile("cp.async.cg.shared.global [%0], [%1], 16;" :: "r"(dst), "l"(src))
#define CP_COMMIT() asm volatile("cp.async.commit_group;" ::: "memory")
#define CP_WAIT0()  asm volatile("cp.async.wait_group 0;" ::: "memory")
#define CP_WAIT1()  asm volatile("cp.async.wait_group 1;" ::: "memory")

__device__ __forceinline__ void ldm_x4(uint32_t* r, uint32_t addr) {
    asm volatile("ldmatrix.sync.aligned.m8n8.x4.shared.b16 {%0,%1,%2,%3}, [%4];"
                 : "=r"(r[0]), "=r"(r[1]), "=r"(r[2]), "=r"(r[3]) : "r"(addr));
}
__device__ __forceinline__ void mma_bf16(float* d, const uint32_t* a, const uint32_t* b) {
    asm volatile("mma.sync.aligned.m16n8k16.row.col.f32.bf16.bf16.f32 "
        "{%0,%1,%2,%3}, {%4,%5,%6,%7}, {%8,%9}, {%0,%1,%2,%3};"
        : "+f"(d[0]), "+f"(d[1]), "+f"(d[2]), "+f"(d[3])
        : "r"(a[0]), "r"(a[1]), "r"(a[2]), "r"(a[3]), "r"(b[0]), "r"(b[1]));
}

// ---------------------------------------------------------------------------
// Split fp32 -> bf16 hi/lo
// ---------------------------------------------------------------------------
__global__ void split_f32(const float* __restrict__ in, __nv_bfloat16* __restrict__ h,
                          __nv_bfloat16* __restrict__ l, int n)
{
    int i = blockIdx.x * blockDim.x + threadIdx.x;
    if (i < n) {
        float x = in[i];
        __nv_bfloat16 hi = __float2bfloat16(x);
        h[i] = hi;
        l[i] = __float2bfloat16(x - __bfloat162float(hi));
    }
}

// ---------------------------------------------------------------------------
// RMSNorm + RoPE -> split bf16 in [b,h,s,d] layout. One warp per (b,s,h).
// ---------------------------------------------------------------------------
__global__ void norm_rope_split(const float* __restrict__ t, const float* __restrict__ scale,
                                const float* __restrict__ cosT, const float* __restrict__ sinT,
                                __nv_bfloat16* __restrict__ oh, __nv_bfloat16* __restrict__ ol,
                                float postmul)
{
    int warp = (blockIdx.x * blockDim.x + threadIdx.x) >> 5;
    int lane = threadIdx.x & 31;

    const float2* row = reinterpret_cast<const float2*>(t + (size_t)warp * 64);
    float2 v = row[lane];

    float ss = v.x * v.x + v.y * v.y;
#pragma unroll
    for (int m = 16; m >= 1; m >>= 1) ss += __shfl_xor_sync(0xffffffffu, ss, m);
    float r = rsqrtf(ss * (1.0f / 64.0f) + EPSV);

    int s = (warp >> 4) & (SEQ - 1);
    int h = warp & 15;
    int b = warp >> 15;
    float c  = cosT[s * 32 + lane];
    float sn = sinT[s * 32 + lane];

    float tr = v.x * r * scale[2 * lane];
    float ti = v.y * r * scale[2 * lane + 1];
    float ox = (tr * c - ti * sn) * postmul;
    float oy = (tr * sn + ti * c) * postmul;

    int z = b * NH + h;
    size_t off = ((size_t)z * SEQ + s) * HD + 2 * lane;
    __nv_bfloat16 hx = __float2bfloat16(ox), hy = __float2bfloat16(oy);
    __nv_bfloat162 hp; hp.x = hx; hp.y = hy;
    *(__nv_bfloat162*)(oh + off) = hp;
    __nv_bfloat162 lp;
    lp.x = __float2bfloat16(ox - __bfloat162float(hx));
    lp.y = __float2bfloat16(oy - __bfloat162float(hy));
    *(__nv_bfloat162*)(ol + off) = lp;
}

// ---------------------------------------------------------------------------
// V: [b,s,h,d] fp32 -> transposed split bf16 [b,h,d,s]
// ---------------------------------------------------------------------------
__global__ void vt_split(const float* __restrict__ vf, __nv_bfloat16* __restrict__ vh,
                         __nv_bfloat16* __restrict__ vl)
{
    __shared__ float t[32][33];
    int z = blockIdx.z, b = z >> 4, h = z & 15;
    int s0 = blockIdx.x * 32, d0 = blockIdx.y * 32;
    for (int i = threadIdx.y; i < 32; i += 8) {
        int s = s0 + i, d = d0 + threadIdx.x;
        t[i][threadIdx.x] = vf[((size_t)(b * SEQ + s)) * DM + h * HD + d];
    }
    __syncthreads();
    for (int i = threadIdx.y; i < 32; i += 8) {
        int d = d0 + i, s = s0 + threadIdx.x;
        float v = t[threadIdx.x][i];
        __nv_bfloat16 hi = __float2bfloat16(v);
        size_t o = ((size_t)z * HD + d) * SEQ + s;
        vh[o] = hi;
        vl[o] = __float2bfloat16(v - __bfloat162float(hi));
    }
}

// ---------------------------------------------------------------------------
// Row softmax over 2048 cols; write normalized probs as split bf16.
// One warp per row.
// ---------------------------------------------------------------------------
__global__ void softmax_split(const float* __restrict__ S, __nv_bfloat16* __restrict__ ph,
                              __nv_bfloat16* __restrict__ pl)
{
    int row = (blockIdx.x * blockDim.x + threadIdx.x) >> 5;
    int lane = threadIdx.x & 31;
    const float4* src = (const float4*)(S + (size_t)row * SEQ);

    float4 v[16];
    float mx = -INFINITY;
#pragma unroll
    for (int i = 0; i < 16; i++) {
        v[i] = src[i * 32 + lane];
        mx = fmaxf(mx, fmaxf(fmaxf(v[i].x, v[i].y), fmaxf(v[i].z, v[i].w)));
    }
#pragma unroll
    for (int m = 16; m >= 1; m >>= 1) mx = fmaxf(mx, __shfl_xor_sync(0xffffffffu, mx, m));

    float sum = 0.f;
#pragma unroll
    for (int i = 0; i < 16; i++) {
        v[i].x = __expf(v[i].x - mx); v[i].y = __expf(v[i].y - mx);
        v[i].z = __expf(v[i].z - mx); v[i].w = __expf(v[i].w - mx);
        sum += v[i].x + v[i].y + v[i].z + v[i].w;
    }
#pragma unroll
    for (int m = 16; m >= 1; m >>= 1) sum += __shfl_xor_sync(0xffffffffu, sum, m);
    float inv = 1.0f / sum;

    size_t base = (size_t)row * SEQ;
#pragma unroll
    for (int i = 0; i < 16; i++) {
        float a = v[i].x * inv, bq = v[i].y * inv, c = v[i].z * inv, d = v[i].w * inv;
        size_t off = base + (i * 32 + lane) * 4;
        __nv_bfloat16 ha = __float2bfloat16(a), hb = __float2bfloat16(bq);
        __nv_bfloat16 hc = __float2bfloat16(c), hd = __float2bfloat16(d);
        __nv_bfloat162 p0; p0.x = ha; p0.y = hb;
        __nv_bfloat162 p1; p1.x = hc; p1.y = hd;
        *(__nv_bfloat162*)(ph + off) = p0;
        *(__nv_bfloat162*)(ph + off + 2) = p1;
        __nv_bfloat162 l0, l1;
        l0.x = __float2bfloat16(a - __bfloat162float(ha));
        l0.y = __float2bfloat16(bq - __bfloat162float(hb));
        l1.x = __float2bfloat16(c - __bfloat162float(hc));
        l1.y = __float2bfloat16(d - __bfloat162float(hd));
        *(__nv_bfloat162*)(pl + off) = l0;
        *(__nv_bfloat162*)(pl + off + 2) = l1;
    }
}

// ---------------------------------------------------------------------------
// Warp-mma bf16 NT GEMM with 3-pass split-precision accumulation.
// C[z][m][n] = sum_k A[z][m][k] * B[z][n][k], A = Ah+Al, B = Bh+Bl
// (passes: Ah*Bh, Al*Bh, Ah*Bl). Block tile 128 x BN, BK = 64 bf16.
// 256 threads = 8 warps (4 m x 2 n), warp tile 32 x (BN/2).
// cp.async double-buffered. EPI 0: fp32 C. EPI 1: split-bf16 attn scatter.
// ---------------------------------------------------------------------------
template<int BN, int EPI>
__global__ void __launch_bounds__(256) mm_wm(
    const __nv_bfloat16* __restrict__ Ah, const __nv_bfloat16* __restrict__ Al,
    const __nv_bfloat16* __restrict__ Bh, const __nv_bfloat16* __restrict__ Bl,
    float* __restrict__ Cf, __nv_bfloat16* __restrict__ Oh, __nv_bfloat16* __restrict__ Ol,
    int K, long sA, long bA, long sB, long bB, long sC, long bC)
{
    extern __shared__ char smem[];
    uint32_t raw = smem_to_u32(smem);
    uint32_t base = (raw + 1023u) & ~1023u;
    const uint32_t A_OFF[2] = { base, base + 16384u };
    const uint32_t B_OFF[2] = { base + 32768u, base + 32768u + (uint32_t)BN * 128u };

    const int tid = threadIdx.x;
    const int lane = tid & 31, wid = tid >> 5;
    const int wm = (wid >> 1) * 32;          // 4 m-warps
    const int wn = (wid & 1) * (BN / 2);     // 2 n-warps
    constexpr int NF = BN / 16;              // n8 frag pairs handled as NF/2 x4 loads

    const int z = blockIdx.z;
    const int bm = blockIdx.y * 128;
    const int bn = blockIdx.x * BN;

    const __nv_bfloat16* Ap[3] = { Ah + (size_t)z * bA, Al + (size_t)z * bA, Ah + (size_t)z * bA };
    const __nv_bfloat16* Bp[3] = { Bh + (size_t)z * bB, Bh + (size_t)z * bB, Bl + (size_t)z * bB };

    float acc[2][NF][4];
#pragma unroll
    for (int i = 0; i < 2; i++)
#pragma unroll
        for (int j = 0; j < NF; j++)
#pragma unroll
            for (int q = 0; q < 4; q++) acc[i][j][q] = 0.f;

    const int kc = K >> 6;
    const int nch = kc * 3;

    auto load_chunk = [&](int c) {
        int p = c / kc;
        int k0 = (c - p * kc) << 6;
        const __nv_bfloat16* Ab = Ap[p] + (size_t)bm * sA + k0;
        const __nv_bfloat16* Bb = Bp[p] + (size_t)bn * sB + k0;
        int buf = c & 1;
        for (int idx = tid; idx < (128 + BN) * 8; idx += 256) {
            bool isA = idx < 1024;
            int li = isA ? idx : idx - 1024;
            int row = li >> 3, seg = li & 7;
            const __nv_bfloat16* src = (isA ? Ab + (size_t)row * sA : Bb + (size_t)row * sB) + seg * 8;
            uint32_t dst = (isA ? A_OFF[buf] : B_OFF[buf]) +
                           SMEM_SWIZZLE_128B((uint32_t)(row * 128 + seg * 16));
            CP_ASYNC16(dst, src);
        }
        CP_COMMIT();
    };

    load_chunk(0);
    const int lr = lane & 15, kh = lane >> 4;

    for (int c = 0; c < nch; c++) {
        if (c + 1 < nch) { load_chunk(c + 1); CP_WAIT1(); }
        else             { CP_WAIT0(); }
        __syncthreads();
        int buf = c & 1;
#pragma unroll
        for (int kk = 0; kk < 4; kk++) {
            uint32_t afr[2][4];
#pragma unroll
            for (int i = 0; i < 2; i++)
                ldm_x4(afr[i], A_OFF[buf] +
                       SMEM_SWIZZLE_128B((uint32_t)((wm + i * 16 + lr) * 128 + kk * 32 + kh * 16)));
#pragma unroll
            for (int j = 0; j < NF / 2; j++) {
                uint32_t bfr[4];
                ldm_x4(bfr, B_OFF[buf] +
                       SMEM_SWIZZLE_128B((uint32_t)((wn + j * 16 + lr) * 128 + kk * 32 + kh * 16)));
                uint32_t blo[2] = { bfr[0], bfr[2] };
                uint32_t bhi[2] = { bfr[1], bfr[3] };
#pragma unroll
                for (int i = 0; i < 2; i++) {
                    mma_bf16(acc[i][2 * j],     afr[i], blo);
                    mma_bf16(acc[i][2 * j + 1], afr[i], bhi);
                }
            }
        }
        __syncthreads();
    }

    // Epilogue straight from registers
    const int rl = lane >> 2, cl = (lane & 3) * 2;
#pragma unroll
    for (int i = 0; i < 2; i++) {
#pragma unroll
        for (int j = 0; j < NF; j++) {
            int row0 = bm + wm + i * 16 + rl;
            int col  = bn + wn + j * 8 + cl;
            if (EPI == 0) {
                float2 lo; lo.x = acc[i][j][0]; lo.y = acc[i][j][1];
                float2 hi; hi.x = acc[i][j][2]; hi.y = acc[i][j][3];
                *(float2*)(Cf + (size_t)z * bC + (size_t)row0 * sC + col) = lo;
                *(float2*)(Cf + (size_t)z * bC + (size_t)(row0 + 8) * sC + col) = hi;
            } else {
                int b2 = z >> 4, h2 = z & 15;
#pragma unroll
                for (int half = 0; half < 2; half++) {
                    int row = row0 + half * 8;
                    float x0 = acc[i][j][2 * half + 0];
                    float x1 = acc[i][j][2 * half + 1];
                    size_t off = ((size_t)(b2 * SEQ + row)) * DM + h2 * HD + col;
                    __nv_bfloat16 e0 = __float2bfloat16(x0);
                    __nv_bfloat16 e1 = __float2bfloat16(x1);
                    __nv_bfloat162 hp; hp.x = e0; hp.y = e1;
                    *(__nv_bfloat162*)(Oh + off) = hp;
                    __nv_bfloat162 lp;
                    lp.x = __float2bfloat16(x0 - __bfloat162float(e0));
                    lp.y = __float2bfloat16(x1 - __bfloat162float(e1));
                    *(__nv_bfloat162*)(Ol + off) = lp;
                }
            }
        }
    }
}

// ---------------------------------------------------------------------------
extern "C" void kernel_launch(void* const* d_in, const int* in_sizes, int n_in,
                              void* d_out, int out_size)
{
    const float* x        = (const float*)d_in[0];
    const float* wq       = (const float*)d_in[1];
    const float* wk       = (const float*)d_in[2];
    const float* wv       = (const float*)d_in[3];
    const float* wo       = (const float*)d_in[4];
    const float* q_scale  = (const float*)d_in[5];
    const float* k_scale  = (const float*)d_in[6];
    const float* rope_cos = (const float*)d_in[7];
    const float* rope_sin = (const float*)d_in[8];
    float* out = (float*)d_out;

    __nv_bfloat16 *xh, *xl, *wqh, *wql, *wkh, *wkl, *wvh, *wvl, *woh, *wol;
    float *qf, *kf, *vf, *scores;
    __nv_bfloat16 *qbh, *qbl, *kbh, *kbl, *vth, *vtl, *ph, *pl, *ath, *atl;
    cudaGetSymbolAddress((void**)&xh, g_xh);   cudaGetSymbolAddress((void**)&xl, g_xl);
    cudaGetSymbolAddress((void**)&wqh, g_wqh); cudaGetSymbolAddress((void**)&wql, g_wql);
    cudaGetSymbolAddress((void**)&wkh, g_wkh); cudaGetSymbolAddress((void**)&wkl, g_wkl);
    cudaGetSymbolAddress((void**)&wvh, g_wvh); cudaGetSymbolAddress((void**)&wvl, g_wvl);
    cudaGetSymbolAddress((void**)&woh, g_woh); cudaGetSymbolAddress((void**)&wol, g_wol);
    cudaGetSymbolAddress((void**)&qf, g_qf);   cudaGetSymbolAddress((void**)&kf, g_kf);
    cudaGetSymbolAddress((void**)&vf, g_vf);
    cudaGetSymbolAddress((void**)&qbh, g_qbh); cudaGetSymbolAddress((void**)&qbl, g_qbl);
    cudaGetSymbolAddress((void**)&kbh, g_kbh); cudaGetSymbolAddress((void**)&kbl, g_kbl);
    cudaGetSymbolAddress((void**)&vth, g_vth); cudaGetSymbolAddress((void**)&vtl, g_vtl);
    cudaGetSymbolAddress((void**)&scores, g_scores);
    cudaGetSymbolAddress((void**)&ph, g_ph);   cudaGetSymbolAddress((void**)&pl, g_pl);
    cudaGetSymbolAddress((void**)&ath, g_ath); cudaGetSymbolAddress((void**)&atl, g_atl);

    const int SM128 = 1024 + 32768 + 2 * 128 * 128;  // 66560
    const int SM64  = 1024 + 32768 + 2 * 64 * 128;   // 50176
    cudaFuncSetAttribute(mm_wm<128, 0>, cudaFuncAttributeMaxDynamicSharedMemorySize, SM128);
    cudaFuncSetAttribute(mm_wm<64, 1>,  cudaFuncAttributeMaxDynamicSharedMemorySize, SM64);

    const int NXE = BATCH * SEQ * DM;
    const int NWE = DM * DM;

    split_f32<<<(NXE + 255) / 256, 256>>>(x, xh, xl, NXE);
    split_f32<<<(NWE + 255) / 256, 256>>>(wq, wqh, wql, NWE);
    split_f32<<<(NWE + 255) / 256, 256>>>(wk, wkh, wkl, NWE);
    split_f32<<<(NWE + 255) / 256, 256>>>(wv, wvh, wvl, NWE);
    split_f32<<<(NWE + 255) / 256, 256>>>(wo, woh, wol, NWE);

    // Projections: [4096,1024] = x * W^T
    dim3 pg(DM / 128, (BATCH * SEQ) / 128, 1);
    mm_wm<128, 0><<<pg, 256, SM128>>>(xh, xl, wqh, wql, qf, nullptr, nullptr,
                                      DM, DM, 0L, DM, 0L, DM, 0L);
    mm_wm<128, 0><<<pg, 256, SM128>>>(xh, xl, wkh, wkl, kf, nullptr, nullptr,
                                      DM, DM, 0L, DM, 0L, DM, 0L);
    mm_wm<128, 0><<<pg, 256, SM128>>>(xh, xl, wvh, wvl, vf, nullptr, nullptr,
                                      DM, DM, 0L, DM, 0L, DM, 0L);

    // RMSNorm + RoPE -> split bf16 per-head layout (q carries 1/sqrt(HD))
    int nblocks = (BATCH * SEQ * NH) / 8;
    norm_rope_split<<<nblocks, 256>>>(qf, q_scale, rope_cos, rope_sin, qbh, qbl, 0.125f);
    norm_rope_split<<<nblocks, 256>>>(kf, k_scale, rope_cos, rope_sin, kbh, kbl, 1.0f);

    // V transpose + split
    vt_split<<<dim3(SEQ / 32, HD / 32, BATCH * NH), dim3(32, 8)>>>(vf, vth, vtl);

    // scores[z][q][k] = Q * K^T
    mm_wm<128, 0><<<dim3(SEQ / 128, SEQ / 128, BATCH * NH), 256, SM128>>>(
        qbh, qbl, kbh, kbl, scores, nullptr, nullptr,
        HD, HD, (long)SEQ * HD, HD, (long)SEQ * HD, SEQ, (long)SEQ * SEQ);

    // softmax -> split bf16 probs
    softmax_split<<<(BATCH * NH * SEQ) / 8, 256>>>(scores, ph, pl);

    // attn = P * V  (epilogue writes split bf16 into [b,s,D] layout)
    mm_wm<64, 1><<<dim3(1, SEQ / 128, BATCH * NH), 256, SM64>>>(
        ph, pl, vth, vtl, nullptr, ath, atl,
        SEQ, SEQ, (long)SEQ * SEQ, SEQ, (long)HD * SEQ, 0L, 0L);

    // out = attn * Wo^T
    mm_wm<128, 0><<<pg, 256, SM128>>>(ath, atl, woh, wol, out, nullptr, nullptr,
                                      DM, DM, 0L, DM, 0L, DM, 0L);
}

// round 4
// speedup vs baseline: 3.5261x; 1.3709x over previous
#include <cuda_runtime.h>
#include <cuda_bf16.h>
#include <cstdint>
#include <math.h>

#define BATCH 2
#define SEQ 2048
#define DM 1024
#define NH 16
#define HD 64
#define EPSV 1e-6f

// ---------------------------------------------------------------------------
// Scratch (__device__ globals: allocation-free rule)
// ---------------------------------------------------------------------------
__device__ __nv_bfloat16 g_xh[BATCH * SEQ * DM];
__device__ __nv_bfloat16 g_xl[BATCH * SEQ * DM];
__device__ __nv_bfloat16 g_wqh[DM * DM], g_wql[DM * DM];
__device__ __nv_bfloat16 g_wkh[DM * DM], g_wkl[DM * DM];
__device__ __nv_bfloat16 g_wvh[DM * DM], g_wvl[DM * DM];
__device__ __nv_bfloat16 g_woh[DM * DM], g_wol[DM * DM];
__device__ float g_qf[BATCH * SEQ * DM];
__device__ float g_kf[BATCH * SEQ * DM];
__device__ float g_vf[BATCH * SEQ * DM];
__device__ __nv_bfloat16 g_qbh[BATCH * NH * SEQ * HD], g_qbl[BATCH * NH * SEQ * HD];
__device__ __nv_bfloat16 g_kbh[BATCH * NH * SEQ * HD], g_kbl[BATCH * NH * SEQ * HD];
__device__ __nv_bfloat16 g_vth[BATCH * NH * HD * SEQ], g_vtl[BATCH * NH * HD * SEQ];
__device__ __nv_bfloat16 g_ath[BATCH * SEQ * DM], g_atl[BATCH * SEQ * DM];

// ---------------------------------------------------------------------------
// Helpers (non-'a' instructions only: legal under compute_103)
// ---------------------------------------------------------------------------
__device__ __forceinline__ uint32_t smem_to_u32(const void* p) {
    uint32_t a;
    asm("{ .reg .u64 t; cvta.to.shared.u64 t, %1; cvt.u32.u64 %0, t; }" : "=r"(a) : "l"(p));
    return a;
}
#define SMEM_SWIZZLE_128B(o) ((o) ^ (((o) >> 3) & 0x70))

#define CP_ASYNC16(dst, src) \
    asm volatile("cp.async.cg.shared.global [%0], [%1], 16;" :: "r"(dst), "l"(src))
#define CP_COMMIT() asm volatile("cp.async.commit_group;" ::: "memory")
#define CP_WAIT0()  asm volatile("cp.async.wait_group 0;" ::: "memory")
#define CP_WAIT1()  asm volatile("cp.async.wait_group 1;" ::: "memory")

__device__ __forceinline__ void ldm_x4(uint32_t* r, uint32_t addr) {
    asm volatile("ldmatrix.sync.aligned.m8n8.x4.shared.b16 {%0,%1,%2,%3}, [%4];"
                 : "=r"(r[0]), "=r"(r[1]), "=r"(r[2]), "=r"(r[3]) : "r"(addr));
}
__device__ __forceinline__ void mma_bf16(float* d, const uint32_t* a, const uint32_t* b) {
    asm volatile("mma.sync.aligned.m16n8k16.row.col.f32.bf16.bf16.f32 "
        "{%0,%1,%2,%3}, {%4,%5,%6,%7}, {%8,%9}, {%0,%1,%2,%3};"
        : "+f"(d[0]), "+f"(d[1]), "+f"(d[2]), "+f"(d[3])
        : "r"(a[0]), "r"(a[1]), "r"(a[2]), "r"(a[3]), "r"(b[0]), "r"(b[1]));
}
__device__ __forceinline__ uint32_t packbf(__nv_bfloat16 lo, __nv_bfloat16 hi) {
    return ((uint32_t)__bfloat16_as_ushort(hi) << 16) | (uint32_t)__bfloat16_as_ushort(lo);
}

// ---------------------------------------------------------------------------
__global__ void split_f32(const float* __restrict__ in, __nv_bfloat16* __restrict__ h,
                          __nv_bfloat16* __restrict__ l, int n)
{
    int i = blockIdx.x * blockDim.x + threadIdx.x;
    if (i < n) {
        float x = in[i];
        __nv_bfloat16 hi = __float2bfloat16(x);
        h[i] = hi;
        l[i] = __float2bfloat16(x - __bfloat162float(hi));
    }
}

// ---------------------------------------------------------------------------
// RMSNorm + RoPE -> split bf16 in [b,h,s,d] layout. One warp per (b,s,h).
// ---------------------------------------------------------------------------
__global__ void norm_rope_split(const float* __restrict__ t, const float* __restrict__ scale,
                                const float* __restrict__ cosT, const float* __restrict__ sinT,
                                __nv_bfloat16* __restrict__ oh, __nv_bfloat16* __restrict__ ol,
                                float postmul)
{
    int warp = (blockIdx.x * blockDim.x + threadIdx.x) >> 5;
    int lane = threadIdx.x & 31;

    const float2* row = reinterpret_cast<const float2*>(t + (size_t)warp * 64);
    float2 v = row[lane];

    float ss = v.x * v.x + v.y * v.y;
#pragma unroll
    for (int m = 16; m >= 1; m >>= 1) ss += __shfl_xor_sync(0xffffffffu, ss, m);
    float r = rsqrtf(ss * (1.0f / 64.0f) + EPSV);

    int s = (warp >> 4) & (SEQ - 1);
    int h = warp & 15;
    int b = warp >> 15;
    float c  = cosT[s * 32 + lane];
    float sn = sinT[s * 32 + lane];

    float tr = v.x * r * scale[2 * lane];
    float ti = v.y * r * scale[2 * lane + 1];
    float ox = (tr * c - ti * sn) * postmul;
    float oy = (tr * sn + ti * c) * postmul;

    int z = b * NH + h;
    size_t off = ((size_t)z * SEQ + s) * HD + 2 * lane;
    __nv_bfloat16 hx = __float2bfloat16(ox), hy = __float2bfloat16(oy);
    __nv_bfloat162 hp; hp.x = hx; hp.y = hy;
    *(__nv_bfloat162*)(oh + off) = hp;
    __nv_bfloat162 lp;
    lp.x = __float2bfloat16(ox - __bfloat162float(hx));
    lp.y = __float2bfloat16(oy - __bfloat162float(hy));
    *(__nv_bfloat162*)(ol + off) = lp;
}

// ---------------------------------------------------------------------------
// V: [b,s,h,d] fp32 -> transposed split bf16 [b,h,d,s]
// ---------------------------------------------------------------------------
__global__ void vt_split(const float* __restrict__ vf, __nv_bfloat16* __restrict__ vh,
                         __nv_bfloat16* __restrict__ vl)
{
    __shared__ float t[32][33];
    int z = blockIdx.z, b = z >> 4, h = z & 15;
    int s0 = blockIdx.x * 32, d0 = blockIdx.y * 32;
    for (int i = threadIdx.y; i < 32; i += 8) {
        int s = s0 + i, d = d0 + threadIdx.x;
        t[i][threadIdx.x] = vf[((size_t)(b * SEQ + s)) * DM + h * HD + d];
    }
    __syncthreads();
    for (int i = threadIdx.y; i < 32; i += 8) {
        int d = d0 + i, s = s0 + threadIdx.x;
        float v = t[threadIdx.x][i];
        __nv_bfloat16 hi = __float2bfloat16(v);
        size_t o = ((size_t)z * HD + d) * SEQ + s;
        vh[o] = hi;
        vl[o] = __float2bfloat16(v - __bfloat162float(hi));
    }
}

// ---------------------------------------------------------------------------
// Warp-mma bf16 NT GEMM, 3-pass split accumulation. fp32 out.
// Block 128x128, BK=64, 8 warps (4m x 2n). (Used for the 4 projections.)
// ---------------------------------------------------------------------------
__global__ void __launch_bounds__(256) mm_wm(
    const __nv_bfloat16* __restrict__ Ah, const __nv_bfloat16* __restrict__ Al,
    const __nv_bfloat16* __restrict__ Bh, const __nv_bfloat16* __restrict__ Bl,
    float* __restrict__ Cf, int K, long sA, long sB, long sC)
{
    extern __shared__ char smem[];
    uint32_t raw = smem_to_u32(smem);
    uint32_t base = (raw + 1023u) & ~1023u;
    const uint32_t A_OFF[2] = { base, base + 16384u };
    const uint32_t B_OFF[2] = { base + 32768u, base + 32768u + 16384u };

    const int tid = threadIdx.x;
    const int lane = tid & 31, wid = tid >> 5;
    const int wm = (wid >> 1) * 32;
    const int wn = (wid & 1) * 64;

    const int bm = blockIdx.y * 128;
    const int bn = blockIdx.x * 128;

    const __nv_bfloat16* Ap[3] = { Ah, Al, Ah };
    const __nv_bfloat16* Bp[3] = { Bh, Bh, Bl };

    float acc[2][8][4];
#pragma unroll
    for (int i = 0; i < 2; i++)
#pragma unroll
        for (int j = 0; j < 8; j++)
#pragma unroll
            for (int q = 0; q < 4; q++) acc[i][j][q] = 0.f;

    const int kc = K >> 6;
    const int nch = kc * 3;

    auto load_chunk = [&](int c) {
        int p = c / kc;
        int k0 = (c - p * kc) << 6;
        const __nv_bfloat16* Ab = Ap[p] + (size_t)bm * sA + k0;
        const __nv_bfloat16* Bb = Bp[p] + (size_t)bn * sB + k0;
        int buf = c & 1;
        for (int idx = tid; idx < 2048; idx += 256) {
            bool isA = idx < 1024;
            int li = idx & 1023;
            int row = li >> 3, seg = li & 7;
            const __nv_bfloat16* src = (isA ? Ab + (size_t)row * sA : Bb + (size_t)row * sB) + seg * 8;
            uint32_t dst = (isA ? A_OFF[buf] : B_OFF[buf]) +
                           SMEM_SWIZZLE_128B((uint32_t)(row * 128 + seg * 16));
            CP_ASYNC16(dst, src);
        }
        CP_COMMIT();
    };

    load_chunk(0);
    const int lr = lane & 15, kh = lane >> 4;

    for (int c = 0; c < nch; c++) {
        if (c + 1 < nch) { load_chunk(c + 1); CP_WAIT1(); }
        else             { CP_WAIT0(); }
        __syncthreads();
        int buf = c & 1;
#pragma unroll
        for (int kk = 0; kk < 4; kk++) {
            uint32_t afr[2][4];
#pragma unroll
            for (int i = 0; i < 2; i++)
                ldm_x4(afr[i], A_OFF[buf] +
                       SMEM_SWIZZLE_128B((uint32_t)((wm + i * 16 + lr) * 128 + kk * 32 + kh * 16)));
#pragma unroll
            for (int j = 0; j < 4; j++) {
                uint32_t bfr[4];
                ldm_x4(bfr, B_OFF[buf] +
                       SMEM_SWIZZLE_128B((uint32_t)((wn + j * 16 + lr) * 128 + kk * 32 + kh * 16)));
                uint32_t blo[2] = { bfr[0], bfr[2] };
                uint32_t bhi[2] = { bfr[1], bfr[3] };
#pragma unroll
                for (int i = 0; i < 2; i++) {
                    mma_bf16(acc[i][2 * j],     afr[i], blo);
                    mma_bf16(acc[i][2 * j + 1], afr[i], bhi);
                }
            }
        }
        __syncthreads();
    }

    const int rl = lane >> 2, cl = (lane & 3) * 2;
#pragma unroll
    for (int i = 0; i < 2; i++)
#pragma unroll
        for (int j = 0; j < 8; j++) {
            int row0 = bm + wm + i * 16 + rl;
            int col  = bn + wn + j * 8 + cl;
            float2 lo; lo.x = acc[i][j][0]; lo.y = acc[i][j][1];
            float2 hi; hi.x = acc[i][j][2]; hi.y = acc[i][j][3];
            *(float2*)(Cf + (size_t)row0 * sC + col) = lo;
            *(float2*)(Cf + (size_t)(row0 + 8) * sC + col) = hi;
        }
}

// ---------------------------------------------------------------------------
// Fused flash attention, mma.sync, split-bf16 3-pass for QK^T and P.V.
// Grid: (SEQ/128, NH, BATCH), 256 threads (8 warps, each 16 q-rows).
// Q (split) resident in smem; K/V tiles of 128 keys double-buffered.
// Output: split bf16 into [b,s,DM] (feeds final projection).
// ---------------------------------------------------------------------------
__global__ void __launch_bounds__(256, 1) flash_attn(
    const __nv_bfloat16* __restrict__ Qh, const __nv_bfloat16* __restrict__ Ql,
    const __nv_bfloat16* __restrict__ Kh, const __nv_bfloat16* __restrict__ Kl,
    const __nv_bfloat16* __restrict__ Vth, const __nv_bfloat16* __restrict__ Vtl,
    __nv_bfloat16* __restrict__ Oh, __nv_bfloat16* __restrict__ Ol)
{
    extern __shared__ char smem[];
    uint32_t raw = smem_to_u32(smem);
    uint32_t base = (raw + 1023u) & ~1023u;
    const uint32_t QH_OFF = base, QL_OFF = base + 16384u;

    const int tid = threadIdx.x;
    const int lane = tid & 31, wid = tid >> 5;
    const int lr = lane & 15, kh4 = lane >> 4;
    const int wm = wid * 16;

    const int z = blockIdx.z * NH + blockIdx.y;
    const int b = blockIdx.z, h = blockIdx.y;
    const int q0 = blockIdx.x * 128;

    const __nv_bfloat16* qh = Qh + ((size_t)z * SEQ + q0) * HD;
    const __nv_bfloat16* ql = Ql + ((size_t)z * SEQ + q0) * HD;
    const __nv_bfloat16* kbh = Kh + (size_t)z * SEQ * HD;
    const __nv_bfloat16* kbl = Kl + (size_t)z * SEQ * HD;
    const __nv_bfloat16* vth = Vth + (size_t)z * HD * SEQ;
    const __nv_bfloat16* vtl = Vtl + (size_t)z * HD * SEQ;

    auto KH_OFF = [&](int buf) { return base + 32768u + (uint32_t)buf * 65536u; };
    auto KL_OFF = [&](int buf) { return KH_OFF(buf) + 16384u; };
    auto VH_OFF = [&](int buf) { return KH_OFF(buf) + 32768u; };
    auto VL_OFF = [&](int buf) { return KH_OFF(buf) + 49152u; };

    // Load Q tile (split) once
    for (int idx = tid; idx < 2048; idx += 256) {
        bool isH = idx < 1024;
        int li = idx & 1023;
        int row = li >> 3, seg = li & 7;
        const __nv_bfloat16* src = (isH ? qh : ql) + (size_t)row * HD + seg * 8;
        uint32_t dst = (isH ? QH_OFF : QL_OFF) + SMEM_SWIZZLE_128B((uint32_t)(row * 128 + seg * 16));
        CP_ASYNC16(dst, src);
    }

    auto load_tile = [&](int kt, int buf) {
        // K tile: 128 keys x 64 d, rows 128B (h + l)
        for (int idx = tid; idx < 2048; idx += 256) {
            bool isH = idx < 1024;
            int li = idx & 1023;
            int row = li >> 3, seg = li & 7;
            const __nv_bfloat16* src = (isH ? kbh : kbl) + (size_t)(kt + row) * HD + seg * 8;
            uint32_t dst = (isH ? KH_OFF(buf) : KL_OFF(buf)) +
                           SMEM_SWIZZLE_128B((uint32_t)(row * 128 + seg * 16));
            CP_ASYNC16(dst, src);
        }
        // V tile: [2 halves][64 d x 64 keys], rows 128B (h + l)
        for (int idx = tid; idx < 2048; idx += 256) {
            bool isH = idx < 1024;
            int li = idx & 1023;
            int d = li >> 4;
            int hk = (li >> 3) & 1, seg = li & 7;
            const __nv_bfloat16* src = (isH ? vth : vtl) + (size_t)d * SEQ + kt + hk * 64 + seg * 8;
            uint32_t dst = (isH ? VH_OFF(buf) : VL_OFF(buf)) + hk * 8192u +
                           SMEM_SWIZZLE_128B((uint32_t)(d * 128 + seg * 16));
            CP_ASYNC16(dst, src);
        }
        CP_COMMIT();
    };

    load_tile(0, 0);
    CP_COMMIT();   // ensure group structure: Q+tile0 committed (Q merged with tile0 groups)

    float m_i[2] = { -INFINITY, -INFINITY };
    float l_i[2] = { 0.f, 0.f };
    float oacc[8][4];
#pragma unroll
    for (int j = 0; j < 8; j++)
#pragma unroll
        for (int q = 0; q < 4; q++) oacc[j][q] = 0.f;

    const int NT = SEQ / 128;
    for (int c = 0; c < NT; c++) {
        int buf = c & 1;
        if (c + 1 < NT) { load_tile((c + 1) * 128, buf ^ 1); CP_WAIT1(); }
        else            { CP_WAIT0(); }
        __syncthreads();

        // ---- S = Q K^T (3-pass split) : per-warp 16 x 128
        float sacc[16][4];
#pragma unroll
        for (int j = 0; j < 16; j++)
#pragma unroll
            for (int q = 0; q < 4; q++) sacc[j][q] = 0.f;

#pragma unroll
        for (int kk = 0; kk < 4; kk++) {
            uint32_t aH[4], aL[4];
            ldm_x4(aH, QH_OFF + SMEM_SWIZZLE_128B((uint32_t)((wm + lr) * 128 + kk * 32 + kh4 * 16)));
            ldm_x4(aL, QL_OFF + SMEM_SWIZZLE_128B((uint32_t)((wm + lr) * 128 + kk * 32 + kh4 * 16)));
#pragma unroll
            for (int nf = 0; nf < 8; nf++) {
                uint32_t addr = SMEM_SWIZZLE_128B((uint32_t)((nf * 16 + lr) * 128 + kk * 32 + kh4 * 16));
                uint32_t bh4[4];
                ldm_x4(bh4, KH_OFF(buf) + addr);
                uint32_t blo[2] = { bh4[0], bh4[2] }, bhi[2] = { bh4[1], bh4[3] };
                mma_bf16(sacc[2 * nf],     aH, blo);
                mma_bf16(sacc[2 * nf + 1], aH, bhi);
                mma_bf16(sacc[2 * nf],     aL, blo);
                mma_bf16(sacc[2 * nf + 1], aL, bhi);
                uint32_t bl4[4];
                ldm_x4(bl4, KL_OFF(buf) + addr);
                uint32_t clo[2] = { bl4[0], bl4[2] }, chi[2] = { bl4[1], bl4[3] };
                mma_bf16(sacc[2 * nf],     aH, clo);
                mma_bf16(sacc[2 * nf + 1], aH, chi);
            }
        }

        // ---- online softmax (rows are warp-local; 4-lane col-group shfl)
        float tmax[2] = { -INFINITY, -INFINITY };
#pragma unroll
        for (int j = 0; j < 16; j++) {
            tmax[0] = fmaxf(tmax[0], fmaxf(sacc[j][0], sacc[j][1]));
            tmax[1] = fmaxf(tmax[1], fmaxf(sacc[j][2], sacc[j][3]));
        }
#pragma unroll
        for (int mk = 1; mk <= 2; mk <<= 1) {
            tmax[0] = fmaxf(tmax[0], __shfl_xor_sync(0xffffffffu, tmax[0], mk));
            tmax[1] = fmaxf(tmax[1], __shfl_xor_sync(0xffffffffu, tmax[1], mk));
        }
        float mnew0 = fmaxf(m_i[0], tmax[0]);
        float mnew1 = fmaxf(m_i[1], tmax[1]);
        float al0 = __expf(m_i[0] - mnew0);
        float al1 = __expf(m_i[1] - mnew1);
        m_i[0] = mnew0; m_i[1] = mnew1;
        float rs0 = 0.f, rs1 = 0.f;
#pragma unroll
        for (int j = 0; j < 16; j++) {
            sacc[j][0] = __expf(sacc[j][0] - mnew0);
            sacc[j][1] = __expf(sacc[j][1] - mnew0);
            sacc[j][2] = __expf(sacc[j][2] - mnew1);
            sacc[j][3] = __expf(sacc[j][3] - mnew1);
            rs0 += sacc[j][0] + sacc[j][1];
            rs1 += sacc[j][2] + sacc[j][3];
        }
#pragma unroll
        for (int mk = 1; mk <= 2; mk <<= 1) {
            rs0 += __shfl_xor_sync(0xffffffffu, rs0, mk);
            rs1 += __shfl_xor_sync(0xffffffffu, rs1, mk);
        }
        l_i[0] = l_i[0] * al0 + rs0;
        l_i[1] = l_i[1] * al1 + rs1;
#pragma unroll
        for (int j = 0; j < 8; j++) {
            oacc[j][0] *= al0; oacc[j][1] *= al0;
            oacc[j][2] *= al1; oacc[j][3] *= al1;
        }

        // ---- O += P V (3-pass split); P fragments built in-register
#pragma unroll
        for (int kk = 0; kk < 8; kk++) {
            float p0 = sacc[2 * kk][0],     p1 = sacc[2 * kk][1];
            float p2 = sacc[2 * kk][2],     p3 = sacc[2 * kk][3];
            float p4 = sacc[2 * kk + 1][0], p5 = sacc[2 * kk + 1][1];
            float p6 = sacc[2 * kk + 1][2], p7 = sacc[2 * kk + 1][3];
            __nv_bfloat16 h0 = __float2bfloat16(p0), h1 = __float2bfloat16(p1);
            __nv_bfloat16 h2 = __float2bfloat16(p2), h3 = __float2bfloat16(p3);
            __nv_bfloat16 h4 = __float2bfloat16(p4), h5 = __float2bfloat16(p5);
            __nv_bfloat16 h6 = __float2bfloat16(p6), h7 = __float2bfloat16(p7);
            uint32_t ah[4] = { packbf(h0, h1), packbf(h2, h3), packbf(h4, h5), packbf(h6, h7) };
            uint32_t alr[4] = {
                packbf(__float2bfloat16(p0 - __bfloat162float(h0)), __float2bfloat16(p1 - __bfloat162float(h1))),
                packbf(__float2bfloat16(p2 - __bfloat162float(h2)), __float2bfloat16(p3 - __bfloat162float(h3))),
                packbf(__float2bfloat16(p4 - __bfloat162float(h4)), __float2bfloat16(p5 - __bfloat162float(h5))),
                packbf(__float2bfloat16(p6 - __bfloat162float(h6)), __float2bfloat16(p7 - __bfloat162float(h7)))
            };
            int hk = kk >> 2, kv = kk & 3;
#pragma unroll
            for (int nfp = 0; nfp < 4; nfp++) {
                uint32_t addr = hk * 8192u +
                    SMEM_SWIZZLE_128B((uint32_t)((nfp * 16 + lr) * 128 + kv * 32 + kh4 * 16));
                uint32_t bh4[4];
                ldm_x4(bh4, VH_OFF(buf) + addr);
                uint32_t blo[2] = { bh4[0], bh4[2] }, bhi[2] = { bh4[1], bh4[3] };
                mma_bf16(oacc[2 * nfp],     ah, blo);
                mma_bf16(oacc[2 * nfp + 1], ah, bhi);
                mma_bf16(oacc[2 * nfp],     alr, blo);
                mma_bf16(oacc[2 * nfp + 1], alr, bhi);
                uint32_t bl4[4];
                ldm_x4(bl4, VL_OFF(buf) + addr);
                uint32_t clo[2] = { bl4[0], bl4[2] }, chi[2] = { bl4[1], bl4[3] };
                mma_bf16(oacc[2 * nfp],     ah, clo);
                mma_bf16(oacc[2 * nfp + 1], ah, chi);
            }
        }
        __syncthreads();
    }

    // ---- epilogue: normalize, split-bf16 write to [b,s,DM]
    float inv0 = 1.0f / l_i[0], inv1 = 1.0f / l_i[1];
    int row0 = q0 + wm + (lane >> 2);
    int colb = h * HD + (lane & 3) * 2;
#pragma unroll
    for (int j = 0; j < 8; j++) {
        float x0 = oacc[j][0] * inv0, x1 = oacc[j][1] * inv0;
        float x2 = oacc[j][2] * inv1, x3 = oacc[j][3] * inv1;
        size_t off0 = ((size_t)(b * SEQ + row0)) * DM + colb + j * 8;
        size_t off1 = ((size_t)(b * SEQ + row0 + 8)) * DM + colb + j * 8;
        __nv_bfloat16 e0 = __float2bfloat16(x0), e1 = __float2bfloat16(x1);
        __nv_bfloat16 e2 = __float2bfloat16(x2), e3 = __float2bfloat16(x3);
        __nv_bfloat162 hp0; hp0.x = e0; hp0.y = e1;
        __nv_bfloat162 hp1; hp1.x = e2; hp1.y = e3;
        *(__nv_bfloat162*)(Oh + off0) = hp0;
        *(__nv_bfloat162*)(Oh + off1) = hp1;
        __nv_bfloat162 lp0, lp1;
        lp0.x = __float2bfloat16(x0 - __bfloat162float(e0));
        lp0.y = __float2bfloat16(x1 - __bfloat162float(e1));
        lp1.x = __float2bfloat16(x2 - __bfloat162float(e2));
        lp1.y = __float2bfloat16(x3 - __bfloat162float(e3));
        *(__nv_bfloat162*)(Ol + off0) = lp0;
        *(__nv_bfloat162*)(Ol + off1) = lp1;
    }
}

// ---------------------------------------------------------------------------
extern "C" void kernel_launch(void* const* d_in, const int* in_sizes, int n_in,
                              void* d_out, int out_size)
{
    const float* x        = (const float*)d_in[0];
    const float* wq       = (const float*)d_in[1];
    const float* wk       = (const float*)d_in[2];
    const float* wv       = (const float*)d_in[3];
    const float* wo       = (const float*)d_in[4];
    const float* q_scale  = (const float*)d_in[5];
    const float* k_scale  = (const float*)d_in[6];
    const float* rope_cos = (const float*)d_in[7];
    const float* rope_sin = (const float*)d_in[8];
    float* out = (float*)d_out;

    __nv_bfloat16 *xh, *xl, *wqh, *wql, *wkh, *wkl, *wvh, *wvl, *woh, *wol;
    float *qf, *kf, *vf;
    __nv_bfloat16 *qbh, *qbl, *kbh, *kbl, *vth, *vtl, *ath, *atl;
    cudaGetSymbolAddress((void**)&xh, g_xh);   cudaGetSymbolAddress((void**)&xl, g_xl);
    cudaGetSymbolAddress((void**)&wqh, g_wqh); cudaGetSymbolAddress((void**)&wql, g_wql);
    cudaGetSymbolAddress((void**)&wkh, g_wkh); cudaGetSymbolAddress((void**)&wkl, g_wkl);
    cudaGetSymbolAddress((void**)&wvh, g_wvh); cudaGetSymbolAddress((void**)&wvl, g_wvl);
    cudaGetSymbolAddress((void**)&woh, g_woh); cudaGetSymbolAddress((void**)&wol, g_wol);
    cudaGetSymbolAddress((void**)&qf, g_qf);   cudaGetSymbolAddress((void**)&kf, g_kf);
    cudaGetSymbolAddress((void**)&vf, g_vf);
    cudaGetSymbolAddress((void**)&qbh, g_qbh); cudaGetSymbolAddress((void**)&qbl, g_qbl);
    cudaGetSymbolAddress((void**)&kbh, g_kbh); cudaGetSymbolAddress((void**)&kbl, g_kbl);
    cudaGetSymbolAddress((void**)&vth, g_vth); cudaGetSymbolAddress((void**)&vtl, g_vtl);
    cudaGetSymbolAddress((void**)&ath, g_ath); cudaGetSymbolAddress((void**)&atl, g_atl);

    const int SMG = 1024 + 65536;              // mm_wm: 64KB tiles + align
    const int SMF = 1024 + 32768 + 2 * 65536;  // flash: Q + 2 buffers = 165KB
    cudaFuncSetAttribute(mm_wm, cudaFuncAttributeMaxDynamicSharedMemorySize, SMG);
    cudaFuncSetAttribute(flash_attn, cudaFuncAttributeMaxDynamicSharedMemorySize, SMF);

    const int NXE = BATCH * SEQ * DM;
    const int NWE = DM * DM;

    split_f32<<<(NXE + 255) / 256, 256>>>(x, xh, xl, NXE);
    split_f32<<<(NWE + 255) / 256, 256>>>(wq, wqh, wql, NWE);
    split_f32<<<(NWE + 255) / 256, 256>>>(wk, wkh, wkl, NWE);
    split_f32<<<(NWE + 255) / 256, 256>>>(wv, wvh, wvl, NWE);
    split_f32<<<(NWE + 255) / 256, 256>>>(wo, woh, wol, NWE);

    dim3 pg(DM / 128, (BATCH * SEQ) / 128);
    mm_wm<<<pg, 256, SMG>>>(xh, xl, wqh, wql, qf, DM, DM, DM, DM);
    mm_wm<<<pg, 256, SMG>>>(xh, xl, wkh, wkl, kf, DM, DM, DM, DM);
    mm_wm<<<pg, 256, SMG>>>(xh, xl, wvh, wvl, vf, DM, DM, DM, DM);

    int nblocks = (BATCH * SEQ * NH) / 8;
    norm_rope_split<<<nblocks, 256>>>(qf, q_scale, rope_cos, rope_sin, qbh, qbl, 0.125f);
    norm_rope_split<<<nblocks, 256>>>(kf, k_scale, rope_cos, rope_sin, kbh, kbl, 1.0f);

    vt_split<<<dim3(SEQ / 32, HD / 32, BATCH * NH), dim3(32, 8)>>>(vf, vth, vtl);

    flash_attn<<<dim3(SEQ / 128, NH, BATCH), 256, SMF>>>(qbh, qbl, kbh, kbl, vth, vtl, ath, atl);

    mm_wm<<<pg, 256, SMG>>>(ath, atl, woh, wol, out, DM, DM, DM, DM);
}

// round 6
// speedup vs baseline: 4.8174x; 1.3662x over previous
#include <cuda_runtime.h>
#include <cuda_fp16.h>
#include <cstdint>
#include <math.h>

#define BATCH 2
#define SEQ 2048
#define DM 1024
#define NH 16
#define HD 64
#define EPSV 1e-6f

// ---------------------------------------------------------------------------
// Scratch (__device__ globals: allocation-free rule)
// ---------------------------------------------------------------------------
__device__ __half g_xh[BATCH * SEQ * DM];
__device__ __half g_xl[BATCH * SEQ * DM];
__device__ __half g_wqh[DM * DM], g_wkh[DM * DM], g_wvh[DM * DM], g_woh[DM * DM];
__device__ float g_qf[BATCH * SEQ * DM];
__device__ float g_kf[BATCH * SEQ * DM];
__device__ float g_vf[BATCH * SEQ * DM];
__device__ __half g_qbh[BATCH * NH * SEQ * HD], g_qbl[BATCH * NH * SEQ * HD];
__device__ __half g_kbh[BATCH * NH * SEQ * HD];
__device__ __half g_vth[BATCH * NH * HD * SEQ];
__device__ __half g_ath[BATCH * SEQ * DM], g_atl[BATCH * SEQ * DM];

// ---------------------------------------------------------------------------
// Helpers (non-'a' instructions only: legal under compute_103)
// ---------------------------------------------------------------------------
__device__ __forceinline__ uint32_t smem_to_u32(const void* p) {
    uint32_t a;
    asm("{ .reg .u64 t; cvta.to.shared.u64 t, %1; cvt.u32.u64 %0, t; }" : "=r"(a) : "l"(p));
    return a;
}
#define SMEM_SWIZZLE_128B(o) ((o) ^ (((o) >> 3) & 0x70))

#define CP_ASYNC16(dst, src) \
    asm volatile("cp.async.cg.shared.global [%0], [%1], 16;" :: "r"(dst), "l"(src))
#define CP_COMMIT() asm volatile("cp.async.commit_group;" ::: "memory")
#define CP_WAIT0()  asm volatile("cp.async.wait_group 0;" ::: "memory")
#define CP_WAIT1()  asm volatile("cp.async.wait_group 1;" ::: "memory")

__device__ __forceinline__ void ldm_x4(uint32_t* r, uint32_t addr) {
    asm volatile("ldmatrix.sync.aligned.m8n8.x4.shared.b16 {%0,%1,%2,%3}, [%4];"
                 : "=r"(r[0]), "=r"(r[1]), "=r"(r[2]), "=r"(r[3]) : "r"(addr));
}
__device__ __forceinline__ void mma_f16(float* d, const uint32_t* a, const uint32_t* b) {
    asm volatile("mma.sync.aligned.m16n8k16.row.col.f32.f16.f16.f32 "
        "{%0,%1,%2,%3}, {%4,%5,%6,%7}, {%8,%9}, {%0,%1,%2,%3};"
        : "+f"(d[0]), "+f"(d[1]), "+f"(d[2]), "+f"(d[3])
        : "r"(a[0]), "r"(a[1]), "r"(a[2]), "r"(a[3]), "r"(b[0]), "r"(b[1]));
}
__device__ __forceinline__ uint32_t packh(__half lo, __half hi) {
    return ((uint32_t)__half_as_ushort(hi) << 16) | (uint32_t)__half_as_ushort(lo);
}

// ---------------------------------------------------------------------------
// fp32 -> fp16 hi/lo split, and hi-only convert
// ---------------------------------------------------------------------------
__global__ void split_f32h(const float* __restrict__ in, __half* __restrict__ h,
                           __half* __restrict__ l, int n)
{
    int i = blockIdx.x * blockDim.x + threadIdx.x;
    if (i < n) {
        float x = in[i];
        __half hi = __float2half_rn(x);
        h[i] = hi;
        l[i] = __float2half_rn(x - __half2float(hi));
    }
}
__global__ void conv_f32h(const float* __restrict__ in, __half* __restrict__ h, int n)
{
    int i = blockIdx.x * blockDim.x + threadIdx.x;
    if (i < n) h[i] = __float2half_rn(in[i]);
}

// ---------------------------------------------------------------------------
// RMSNorm + RoPE -> fp16 in [b,h,s,d] layout. One warp per (b,s,h).
// LO=true also writes the fp16 residual (corrected operand).
// ---------------------------------------------------------------------------
template<bool LO>
__global__ void norm_rope_h(const float* __restrict__ t, const float* __restrict__ scale,
                            const float* __restrict__ cosT, const float* __restrict__ sinT,
                            __half* __restrict__ oh, __half* __restrict__ ol, float postmul)
{
    int warp = (blockIdx.x * blockDim.x + threadIdx.x) >> 5;
    int lane = threadIdx.x & 31;

    const float2* row = reinterpret_cast<const float2*>(t + (size_t)warp * 64);
    float2 v = row[lane];

    float ss = v.x * v.x + v.y * v.y;
#pragma unroll
    for (int m = 16; m >= 1; m >>= 1) ss += __shfl_xor_sync(0xffffffffu, ss, m);
    float r = rsqrtf(ss * (1.0f / 64.0f) + EPSV);

    int s = (warp >> 4) & (SEQ - 1);
    int h = warp & 15;
    int b = warp >> 15;
    float c  = cosT[s * 32 + lane];
    float sn = sinT[s * 32 + lane];

    float tr = v.x * r * scale[2 * lane];
    float ti = v.y * r * scale[2 * lane + 1];
    float ox = (tr * c - ti * sn) * postmul;
    float oy = (tr * sn + ti * c) * postmul;

    int z = b * NH + h;
    size_t off = ((size_t)z * SEQ + s) * HD + 2 * lane;
    __half hx = __float2half_rn(ox), hy = __float2half_rn(oy);
    __half2 hp; hp.x = hx; hp.y = hy;
    *(__half2*)(oh + off) = hp;
    if (LO) {
        __half2 lp;
        lp.x = __float2half_rn(ox - __half2float(hx));
        lp.y = __float2half_rn(oy - __half2float(hy));
        *(__half2*)(ol + off) = lp;
    }
}

// ---------------------------------------------------------------------------
// V: [b,s,h,d] fp32 -> transposed fp16 [b,h,d,s]  (hi only: uncorrected operand)
// ---------------------------------------------------------------------------
__global__ void vt_h(const float* __restrict__ vf, __half* __restrict__ vh)
{
    __shared__ float t[32][33];
    int z = blockIdx.z, b = z >> 4, h = z & 15;
    int s0 = blockIdx.x * 32, d0 = blockIdx.y * 32;
    for (int i = threadIdx.y; i < 32; i += 8) {
        int s = s0 + i, d = d0 + threadIdx.x;
        t[i][threadIdx.x] = vf[((size_t)(b * SEQ + s)) * DM + h * HD + d];
    }
    __syncthreads();
    for (int i = threadIdx.y; i < 32; i += 8) {
        int d = d0 + i, s = s0 + threadIdx.x;
        vh[((size_t)z * HD + d) * SEQ + s] = __float2half_rn(t[threadIdx.x][i]);
    }
}

// ---------------------------------------------------------------------------
// Warp-mma fp16 NT GEMM, 2-pass split (A = Ah+Al corrected, B = Bh). fp32 out.
// Block 128x128, BK=64. 8 warps (4m x 2n). Per chunk load {Ah, Al, Bh}.
// ---------------------------------------------------------------------------
__global__ void __launch_bounds__(256) mm_wm(
    const __half* __restrict__ Ah, const __half* __restrict__ Al,
    const __half* __restrict__ Bh, float* __restrict__ Cf,
    int K, long sA, long sB, long sC)
{
    extern __shared__ char smem[];
    uint32_t raw = smem_to_u32(smem);
    uint32_t base = (raw + 1023u) & ~1023u;
    // per-buffer block: {Ah 16K, Al 16K, Bh 16K}
    auto AH_OFF = [&](int buf) { return base + (uint32_t)buf * 49152u; };
    auto AL_OFF = [&](int buf) { return AH_OFF(buf) + 16384u; };
    auto BH_OFF = [&](int buf) { return AH_OFF(buf) + 32768u; };

    const int tid = threadIdx.x;
    const int lane = tid & 31, wid = tid >> 5;
    const int wm = (wid >> 1) * 32;
    const int wn = (wid & 1) * 64;

    const int bm = blockIdx.y * 128;
    const int bn = blockIdx.x * 128;

    float acc[2][8][4];
#pragma unroll
    for (int i = 0; i < 2; i++)
#pragma unroll
        for (int j = 0; j < 8; j++)
#pragma unroll
            for (int q = 0; q < 4; q++) acc[i][j][q] = 0.f;

    const int kc = K >> 6;

    auto load_chunk = [&](int c) {
        int k0 = c << 6;
        int buf = c & 1;
        // 3 x 1024 segments of 16B
        for (int idx = tid; idx < 3072; idx += 256) {
            int sel = idx >> 10;          // 0 = Ah, 1 = Al, 2 = Bh
            int li = idx & 1023;
            int row = li >> 3, seg = li & 7;
            const __half* src;
            uint32_t dstb;
            if (sel == 0)      { src = Ah + (size_t)(bm + row) * sA + k0; dstb = AH_OFF(buf); }
            else if (sel == 1) { src = Al + (size_t)(bm + row) * sA + k0; dstb = AL_OFF(buf); }
            else               { src = Bh + (size_t)(bn + row) * sB + k0; dstb = BH_OFF(buf); }
            CP_ASYNC16(dstb + SMEM_SWIZZLE_128B((uint32_t)(row * 128 + seg * 16)), src + seg * 8);
        }
        CP_COMMIT();
    };

    load_chunk(0);
    const int lr = lane & 15, kh = lane >> 4;

    for (int c = 0; c < kc; c++) {
        if (c + 1 < kc) { load_chunk(c + 1); CP_WAIT1(); }
        else            { CP_WAIT0(); }
        __syncthreads();
        int buf = c & 1;
#pragma unroll
        for (int kk = 0; kk < 4; kk++) {
            uint32_t aH[2][4], aL[2][4];
#pragma unroll
            for (int i = 0; i < 2; i++) {
                uint32_t ra = SMEM_SWIZZLE_128B((uint32_t)((wm + i * 16 + lr) * 128 + kk * 32 + kh * 16));
                ldm_x4(aH[i], AH_OFF(buf) + ra);
                ldm_x4(aL[i], AL_OFF(buf) + ra);
            }
#pragma unroll
            for (int j = 0; j < 4; j++) {
                uint32_t bfr[4];
                ldm_x4(bfr, BH_OFF(buf) +
                       SMEM_SWIZZLE_128B((uint32_t)((wn + j * 16 + lr) * 128 + kk * 32 + kh * 16)));
                uint32_t blo[2] = { bfr[0], bfr[2] };
                uint32_t bhi[2] = { bfr[1], bfr[3] };
#pragma unroll
                for (int i = 0; i < 2; i++) {
                    mma_f16(acc[i][2 * j],     aH[i], blo);
                    mma_f16(acc[i][2 * j + 1], aH[i], bhi);
                    mma_f16(acc[i][2 * j],     aL[i], blo);
                    mma_f16(acc[i][2 * j + 1], aL[i], bhi);
                }
            }
        }
        __syncthreads();
    }

    const int rl = lane >> 2, cl = (lane & 3) * 2;
#pragma unroll
    for (int i = 0; i < 2; i++)
#pragma unroll
        for (int j = 0; j < 8; j++) {
            int row0 = bm + wm + i * 16 + rl;
            int col  = bn + wn + j * 8 + cl;
            float2 lo; lo.x = acc[i][j][0]; lo.y = acc[i][j][1];
            float2 hi; hi.x = acc[i][j][2]; hi.y = acc[i][j][3];
            *(float2*)(Cf + (size_t)row0 * sC + col) = lo;
            *(float2*)(Cf + (size_t)(row0 + 8) * sC + col) = hi;
        }
}

// ---------------------------------------------------------------------------
// Fused flash attention, fp16 mma, 2-pass split (Q and P corrected; K, V hi).
// Grid: (SEQ/128, NH, BATCH), 256 threads (8 warps, each 16 q-rows).
// ---------------------------------------------------------------------------
__global__ void __launch_bounds__(256, 1) flash_attn(
    const __half* __restrict__ Qh, const __half* __restrict__ Ql,
    const __half* __restrict__ Kh, const __half* __restrict__ Vth,
    __half* __restrict__ Oh, __half* __restrict__ Ol)
{
    extern __shared__ char smem[];
    uint32_t raw = smem_to_u32(smem);
    uint32_t base = (raw + 1023u) & ~1023u;
    const uint32_t QH_OFF = base, QL_OFF = base + 16384u;
    auto KH_OFF = [&](int buf) { return base + 32768u + (uint32_t)buf * 32768u; };
    auto VH_OFF = [&](int buf) { return KH_OFF(buf) + 16384u; };

    const int tid = threadIdx.x;
    const int lane = tid & 31, wid = tid >> 5;
    const int lr = lane & 15, kh4 = lane >> 4;
    const int wm = wid * 16;

    const int z = blockIdx.z * NH + blockIdx.y;
    const int b = blockIdx.z, h = blockIdx.y;
    const int q0 = blockIdx.x * 128;

    const __half* qh = Qh + ((size_t)z * SEQ + q0) * HD;
    const __half* ql = Ql + ((size_t)z * SEQ + q0) * HD;
    const __half* kbh = Kh + (size_t)z * SEQ * HD;
    const __half* vth = Vth + (size_t)z * HD * SEQ;

    // Load Q tile (hi+lo); joins tile-0's cp.async group
    for (int idx = tid; idx < 2048; idx += 256) {
        bool isH = idx < 1024;
        int li = idx & 1023;
        int row = li >> 3, seg = li & 7;
        const __half* src = (isH ? qh : ql) + (size_t)row * HD + seg * 8;
        uint32_t dst = (isH ? QH_OFF : QL_OFF) + SMEM_SWIZZLE_128B((uint32_t)(row * 128 + seg * 16));
        CP_ASYNC16(dst, src);
    }

    auto load_tile = [&](int kt, int buf) {
        // K tile hi: 128 keys x 64 d (128B rows)
        for (int idx = tid; idx < 1024; idx += 256) {
            int row = idx >> 3, seg = idx & 7;
            CP_ASYNC16(KH_OFF(buf) + SMEM_SWIZZLE_128B((uint32_t)(row * 128 + seg * 16)),
                       kbh + (size_t)(kt + row) * HD + seg * 8);
        }
        // V tile hi: [2 halves][64 d x 64 keys] (128B rows)
        for (int idx = tid; idx < 1024; idx += 256) {
            int d = idx >> 4;
            int hk = (idx >> 3) & 1, seg = idx & 7;
            CP_ASYNC16(VH_OFF(buf) + hk * 8192u + SMEM_SWIZZLE_128B((uint32_t)(d * 128 + seg * 16)),
                       vth + (size_t)d * SEQ + kt + hk * 64 + seg * 8);
        }
        CP_COMMIT();
    };

    load_tile(0, 0);

    float m_i[2] = { -INFINITY, -INFINITY };
    float l_i[2] = { 0.f, 0.f };
    float oacc[8][4];
#pragma unroll
    for (int j = 0; j < 8; j++)
#pragma unroll
        for (int q = 0; q < 4; q++) oacc[j][q] = 0.f;

    const int NT = SEQ / 128;
    for (int c = 0; c < NT; c++) {
        int buf = c & 1;
        if (c + 1 < NT) { load_tile((c + 1) * 128, buf ^ 1); CP_WAIT1(); }
        else            { CP_WAIT0(); }
        __syncthreads();

        // ---- S = Q K^T (2-pass) : per-warp 16 x 128
        float sacc[16][4];
#pragma unroll
        for (int j = 0; j < 16; j++)
#pragma unroll
            for (int q = 0; q < 4; q++) sacc[j][q] = 0.f;

#pragma unroll
        for (int kk = 0; kk < 4; kk++) {
            uint32_t ra = SMEM_SWIZZLE_128B((uint32_t)((wm + lr) * 128 + kk * 32 + kh4 * 16));
            uint32_t aH[4], aL[4];
            ldm_x4(aH, QH_OFF + ra);
            ldm_x4(aL, QL_OFF + ra);
#pragma unroll
            for (int nf = 0; nf < 8; nf++) {
                uint32_t bh4[4];
                ldm_x4(bh4, KH_OFF(buf) +
                       SMEM_SWIZZLE_128B((uint32_t)((nf * 16 + lr) * 128 + kk * 32 + kh4 * 16)));
                uint32_t blo[2] = { bh4[0], bh4[2] }, bhi[2] = { bh4[1], bh4[3] };
                mma_f16(sacc[2 * nf],     aH, blo);
                mma_f16(sacc[2 * nf + 1], aH, bhi);
                mma_f16(sacc[2 * nf],     aL, blo);
                mma_f16(sacc[2 * nf + 1], aL, bhi);
            }
        }

        // ---- online softmax (rows warp-local; 4-lane col-group shfl)
        float tmax[2] = { -INFINITY, -INFINITY };
#pragma unroll
        for (int j = 0; j < 16; j++) {
            tmax[0] = fmaxf(tmax[0], fmaxf(sacc[j][0], sacc[j][1]));
            tmax[1] = fmaxf(tmax[1], fmaxf(sacc[j][2], sacc[j][3]));
        }
#pragma unroll
        for (int mk = 1; mk <= 2; mk <<= 1) {
            tmax[0] = fmaxf(tmax[0], __shfl_xor_sync(0xffffffffu, tmax[0], mk));
            tmax[1] = fmaxf(tmax[1], __shfl_xor_sync(0xffffffffu, tmax[1], mk));
        }
        float mnew0 = fmaxf(m_i[0], tmax[0]);
        float mnew1 = fmaxf(m_i[1], tmax[1]);
        float al0 = __expf(m_i[0] - mnew0);
        float al1 = __expf(m_i[1] - mnew1);
        m_i[0] = mnew0; m_i[1] = mnew1;
        float rs0 = 0.f, rs1 = 0.f;
#pragma unroll
        for (int j = 0; j < 16; j++) {
            sacc[j][0] = __expf(sacc[j][0] - mnew0);
            sacc[j][1] = __expf(sacc[j][1] - mnew0);
            sacc[j][2] = __expf(sacc[j][2] - mnew1);
            sacc[j][3] = __expf(sacc[j][3] - mnew1);
            rs0 += sacc[j][0] + sacc[j][1];
            rs1 += sacc[j][2] + sacc[j][3];
        }
#pragma unroll
        for (int mk = 1; mk <= 2; mk <<= 1) {
            rs0 += __shfl_xor_sync(0xffffffffu, rs0, mk);
            rs1 += __shfl_xor_sync(0xffffffffu, rs1, mk);
        }
        l_i[0] = l_i[0] * al0 + rs0;
        l_i[1] = l_i[1] * al1 + rs1;
#pragma unroll
        for (int j = 0; j < 8; j++) {
            oacc[j][0] *= al0; oacc[j][1] *= al0;
            oacc[j][2] *= al1; oacc[j][3] *= al1;
        }

        // ---- O += P V (2-pass; P split in-register)
#pragma unroll
        for (int kk = 0; kk < 8; kk++) {
            float p0 = sacc[2 * kk][0],     p1 = sacc[2 * kk][1];
            float p2 = sacc[2 * kk][2],     p3 = sacc[2 * kk][3];
            float p4 = sacc[2 * kk + 1][0], p5 = sacc[2 * kk + 1][1];
            float p6 = sacc[2 * kk + 1][2], p7 = sacc[2 * kk + 1][3];
            __half h0 = __float2half_rn(p0), h1 = __float2half_rn(p1);
            __half h2 = __float2half_rn(p2), h3 = __float2half_rn(p3);
            __half h4 = __float2half_rn(p4), h5 = __float2half_rn(p5);
            __half h6 = __float2half_rn(p6), h7 = __float2half_rn(p7);
            uint32_t ah[4] = { packh(h0, h1), packh(h2, h3), packh(h4, h5), packh(h6, h7) };
            uint32_t alr[4] = {
                packh(__float2half_rn(p0 - __half2float(h0)), __float2half_rn(p1 - __half2float(h1))),
                packh(__float2half_rn(p2 - __half2float(h2)), __float2half_rn(p3 - __half2float(h3))),
                packh(__float2half_rn(p4 - __half2float(h4)), __float2half_rn(p5 - __half2float(h5))),
                packh(__float2half_rn(p6 - __half2float(h6)), __float2half_rn(p7 - __half2float(h7)))
            };
            int hk = kk >> 2, kv = kk & 3;
#pragma unroll
            for (int nfp = 0; nfp < 4; nfp++) {
                uint32_t bh4[4];
                ldm_x4(bh4, VH_OFF(buf) + hk * 8192u +
                       SMEM_SWIZZLE_128B((uint32_t)((nfp * 16 + lr) * 128 + kv * 32 + kh4 * 16)));
                uint32_t blo[2] = { bh4[0], bh4[2] }, bhi[2] = { bh4[1], bh4[3] };
                mma_f16(oacc[2 * nfp],     ah, blo);
                mma_f16(oacc[2 * nfp + 1], ah, bhi);
                mma_f16(oacc[2 * nfp],     alr, blo);
                mma_f16(oacc[2 * nfp + 1], alr, bhi);
            }
        }
        __syncthreads();
    }

    // ---- epilogue: normalize, split-fp16 write to [b,s,DM]
    float inv0 = 1.0f / l_i[0], inv1 = 1.0f / l_i[1];
    int row0 = q0 + wm + (lane >> 2);
    int colb = h * HD + (lane & 3) * 2;
#pragma unroll
    for (int j = 0; j < 8; j++) {
        float x0 = oacc[j][0] * inv0, x1 = oacc[j][1] * inv0;
        float x2 = oacc[j][2] * inv1, x3 = oacc[j][3] * inv1;
        size_t off0 = ((size_t)(b * SEQ + row0)) * DM + colb + j * 8;
        size_t off1 = ((size_t)(b * SEQ + row0 + 8)) * DM + colb + j * 8;
        __half e0 = __float2half_rn(x0), e1 = __float2half_rn(x1);
        __half e2 = __float2half_rn(x2), e3 = __float2half_rn(x3);
        __half2 hp0; hp0.x = e0; hp0.y = e1;
        __half2 hp1; hp1.x = e2; hp1.y = e3;
        *(__half2*)(Oh + off0) = hp0;
        *(__half2*)(Oh + off1) = hp1;
        __half2 lp0, lp1;
        lp0.x = __float2half_rn(x0 - __half2float(e0));
        lp0.y = __float2half_rn(x1 - __half2float(e1));
        lp1.x = __float2half_rn(x2 - __half2float(e2));
        lp1.y = __float2half_rn(x3 - __half2float(e3));
        *(__half2*)(Ol + off0) = lp0;
        *(__half2*)(Ol + off1) = lp1;
    }
}

// ---------------------------------------------------------------------------
extern "C" void kernel_launch(void* const* d_in, const int* in_sizes, int n_in,
                              void* d_out, int out_size)
{
    const float* x        = (const float*)d_in[0];
    const float* wq       = (const float*)d_in[1];
    const float* wk       = (const float*)d_in[2];
    const float* wv       = (const float*)d_in[3];
    const float* wo       = (const float*)d_in[4];
    const float* q_scale  = (const float*)d_in[5];
    const float* k_scale  = (const float*)d_in[6];
    const float* rope_cos = (const float*)d_in[7];
    const float* rope_sin = (const float*)d_in[8];
    float* out = (float*)d_out;

    __half *xh, *xl, *wqh, *wkh, *wvh, *woh;
    float *qf, *kf, *vf;
    __half *qbh, *qbl, *kbh, *vth, *ath, *atl;
    cudaGetSymbolAddress((void**)&xh, g_xh);   cudaGetSymbolAddress((void**)&xl, g_xl);
    cudaGetSymbolAddress((void**)&wqh, g_wqh); cudaGetSymbolAddress((void**)&wkh, g_wkh);
    cudaGetSymbolAddress((void**)&wvh, g_wvh); cudaGetSymbolAddress((void**)&woh, g_woh);
    cudaGetSymbolAddress((void**)&qf, g_qf);   cudaGetSymbolAddress((void**)&kf, g_kf);
    cudaGetSymbolAddress((void**)&vf, g_vf);
    cudaGetSymbolAddress((void**)&qbh, g_qbh); cudaGetSymbolAddress((void**)&qbl, g_qbl);
    cudaGetSymbolAddress((void**)&kbh, g_kbh);
    cudaGetSymbolAddress((void**)&vth, g_vth);
    cudaGetSymbolAddress((void**)&ath, g_ath); cudaGetSymbolAddress((void**)&atl, g_atl);

    const int SMG = 1024 + 2 * 49152;          // mm_wm: 2 x {Ah,Al,Bh} = 99328
    const int SMF = 1024 + 32768 + 2 * 32768;  // flash: Q(hi+lo) + 2 x {Kh,Vh} = 99328
    cudaFuncSetAttribute(mm_wm, cudaFuncAttributeMaxDynamicSharedMemorySize, SMG);
    cudaFuncSetAttribute(flash_attn, cudaFuncAttributeMaxDynamicSharedMemorySize, SMF);

    const int NXE = BATCH * SEQ * DM;
    const int NWE = DM * DM;

    split_f32h<<<(NXE + 255) / 256, 256>>>(x, xh, xl, NXE);
    conv_f32h<<<(NWE + 255) / 256, 256>>>(wq, wqh, NWE);
    conv_f32h<<<(NWE + 255) / 256, 256>>>(wk, wkh, NWE);
    conv_f32h<<<(NWE + 255) / 256, 256>>>(wv, wvh, NWE);
    conv_f32h<<<(NWE + 255) / 256, 256>>>(wo, woh, NWE);

    dim3 pg(DM / 128, (BATCH * SEQ) / 128);
    mm_wm<<<pg, 256, SMG>>>(xh, xl, wqh, qf, DM, DM, DM, DM);
    mm_wm<<<pg, 256, SMG>>>(xh, xl, wkh, kf, DM, DM, DM, DM);
    mm_wm<<<pg, 256, SMG>>>(xh, xl, wvh, vf, DM, DM, DM, DM);

    int nblocks = (BATCH * SEQ * NH) / 8;
    norm_rope_h<true><<<nblocks, 256>>>(qf, q_scale, rope_cos, rope_sin, qbh, qbl, 0.125f);
    norm_rope_h<false><<<nblocks, 256>>>(kf, k_scale, rope_cos, rope_sin, kbh, nullptr, 1.0f);

    vt_h<<<dim3(SEQ / 32, HD / 32, BATCH * NH), dim3(32, 8)>>>(vf, vth);

    flash_attn<<<dim3(SEQ / 128, NH, BATCH), 256, SMF>>>(qbh, qbl, kbh, vth, ath, atl);

    mm_wm<<<pg, 256, SMG>>>(ath, atl, woh, out, DM, DM, DM, DM);
}

// round 7
// speedup vs baseline: 4.9773x; 1.0332x over previous
#include <cuda_runtime.h>
#include <cuda_fp16.h>
#include <cstdint>
#include <math.h>

#define BATCH 2
#define SEQ 2048
#define DM 1024
#define NH 16
#define HD 64
#define EPSV 1e-6f

// ---------------------------------------------------------------------------
// Scratch (__device__ globals: allocation-free rule)
// ---------------------------------------------------------------------------
__device__ __half g_xh[BATCH * SEQ * DM];
__device__ __half g_xl[BATCH * SEQ * DM];
__device__ __half g_wqh[DM * DM], g_wkh[DM * DM], g_wvh[DM * DM], g_woh[DM * DM];
__device__ __half g_qbh[BATCH * NH * SEQ * HD], g_qbl[BATCH * NH * SEQ * HD];
__device__ __half g_kbh[BATCH * NH * SEQ * HD];
__device__ __half g_vh16[BATCH * SEQ * DM];          // [b,s,h,d] fp16
__device__ __half g_vth[BATCH * NH * HD * SEQ];      // [b,h,d,s] fp16
__device__ __half g_ath[BATCH * SEQ * DM], g_atl[BATCH * SEQ * DM];

// ---------------------------------------------------------------------------
// Helpers (non-'a' instructions only: legal under compute_103)
// ---------------------------------------------------------------------------
__device__ __forceinline__ uint32_t smem_to_u32(const void* p) {
    uint32_t a;
    asm("{ .reg .u64 t; cvta.to.shared.u64 t, %1; cvt.u32.u64 %0, t; }" : "=r"(a) : "l"(p));
    return a;
}
#define SMEM_SWIZZLE_128B(o) ((o) ^ (((o) >> 3) & 0x70))

#define CP_ASYNC16(dst, src) \
    asm volatile("cp.async.cg.shared.global [%0], [%1], 16;" :: "r"(dst), "l"(src))
#define CP_COMMIT() asm volatile("cp.async.commit_group;" ::: "memory")
#define CP_WAIT0()  asm volatile("cp.async.wait_group 0;" ::: "memory")
#define CP_WAIT1()  asm volatile("cp.async.wait_group 1;" ::: "memory")

__device__ __forceinline__ void ldm_x4(uint32_t* r, uint32_t addr) {
    asm volatile("ldmatrix.sync.aligned.m8n8.x4.shared.b16 {%0,%1,%2,%3}, [%4];"
                 : "=r"(r[0]), "=r"(r[1]), "=r"(r[2]), "=r"(r[3]) : "r"(addr));
}
__device__ __forceinline__ void mma_f16(float* d, const uint32_t* a, const uint32_t* b) {
    asm volatile("mma.sync.aligned.m16n8k16.row.col.f32.f16.f16.f32 "
        "{%0,%1,%2,%3}, {%4,%5,%6,%7}, {%8,%9}, {%0,%1,%2,%3};"
        : "+f"(d[0]), "+f"(d[1]), "+f"(d[2]), "+f"(d[3])
        : "r"(a[0]), "r"(a[1]), "r"(a[2]), "r"(a[3]), "r"(b[0]), "r"(b[1]));
}
__device__ __forceinline__ uint32_t h2u(__half2 h) { return *reinterpret_cast<uint32_t*>(&h); }

// ---------------------------------------------------------------------------
// x -> fp16 hi/lo split
// ---------------------------------------------------------------------------
__global__ void split_f32h(const float* __restrict__ in, __half* __restrict__ h,
                           __half* __restrict__ l, int n)
{
    int i = blockIdx.x * blockDim.x + threadIdx.x;
    if (i < n) {
        float x = in[i];
        __half hi = __float2half_rn(x);
        h[i] = hi;
        l[i] = __float2half_rn(x - __half2float(hi));
    }
}

// All 4 weights -> fp16 hi in one launch. n = DM*DM per weight.
__global__ void conv_weights(const float* __restrict__ wq, const float* __restrict__ wk,
                             const float* __restrict__ wv, const float* __restrict__ wo,
                             __half* __restrict__ oq, __half* __restrict__ ok,
                             __half* __restrict__ ov, __half* __restrict__ oo)
{
    int i = blockIdx.x * blockDim.x + threadIdx.x;
    int sel = i >> 20, li = i & ((1 << 20) - 1);          // DM*DM = 2^20
    const float* src = sel == 0 ? wq : sel == 1 ? wk : sel == 2 ? wv : wo;
    __half* dst = sel == 0 ? oq : sel == 1 ? ok : sel == 2 ? ov : oo;
    dst[li] = __float2half_rn(src[li]);
}

// ---------------------------------------------------------------------------
// V: [b,s,h,d] fp16 -> transposed fp16 [b,h,d,s]
// ---------------------------------------------------------------------------
__global__ void vt_h16(const __half* __restrict__ vf, __half* __restrict__ vh)
{
    __shared__ __half t[32][34];
    int z = blockIdx.z, b = z >> 4, h = z & 15;
    int s0 = blockIdx.x * 32, d0 = blockIdx.y * 32;
    for (int i = threadIdx.y; i < 32; i += 8) {
        int s = s0 + i, d = d0 + threadIdx.x;
        t[i][threadIdx.x] = vf[((size_t)(b * SEQ + s)) * DM + h * HD + d];
    }
    __syncthreads();
    for (int i = threadIdx.y; i < 32; i += 8) {
        int d = d0 + i, s = s0 + threadIdx.x;
        vh[((size_t)z * HD + d) * SEQ + s] = t[threadIdx.x][i];
    }
}

// ---------------------------------------------------------------------------
// Warp-mma fp16 NT GEMM, 2-pass split (A = Ah+Al, B = Bh hi-only).
// Block 128x128, BK=64, 8 warps (4m x 2n), warp tile 32x64.
// EPI 0: fp32 C [M,DM]                      (final projection)
// EPI 1: RMSNorm+RoPE -> split fp16 [b,h,s,d]; blockIdx.z: 0=Q(hi+lo),1=K(hi)
// EPI 2: plain fp16 [b,s,h,d]               (V projection)
// ---------------------------------------------------------------------------
template<int EPI>
__global__ void __launch_bounds__(256) proj_mm(
    const __half* __restrict__ Ah, const __half* __restrict__ Al,
    const __half* __restrict__ B0, const __half* __restrict__ B1,
    float* __restrict__ Cf,
    __half* __restrict__ OutH, __half* __restrict__ OutL, __half* __restrict__ OutK,
    const float* __restrict__ qscale, const float* __restrict__ kscale,
    const float* __restrict__ cosT, const float* __restrict__ sinT)
{
    extern __shared__ char smem[];
    uint32_t raw = smem_to_u32(smem);
    uint32_t base = (raw + 1023u) & ~1023u;
    auto AH_OFF = [&](int buf) { return base + (uint32_t)buf * 49152u; };
    auto AL_OFF = [&](int buf) { return AH_OFF(buf) + 16384u; };
    auto BH_OFF = [&](int buf) { return AH_OFF(buf) + 32768u; };

    const int tid = threadIdx.x;
    const int lane = tid & 31, wid = tid >> 5;
    const int wm = (wid >> 1) * 32;
    const int wn = (wid & 1) * 64;

    const int bm = blockIdx.y * 128;
    const int bn = blockIdx.x * 128;
    const int zb = (EPI == 1) ? blockIdx.z : 0;
    const __half* Bh = (EPI == 1 && zb == 1) ? B1 : B0;

    float acc[2][8][4];
#pragma unroll
    for (int i = 0; i < 2; i++)
#pragma unroll
        for (int j = 0; j < 8; j++)
#pragma unroll
            for (int q = 0; q < 4; q++) acc[i][j][q] = 0.f;

    auto load_chunk = [&](int c) {
        int k0 = c << 6;
        int buf = c & 1;
        for (int idx = tid; idx < 3072; idx += 256) {
            int sel = idx >> 10;
            int li = idx & 1023;
            int row = li >> 3, seg = li & 7;
            const __half* src;
            uint32_t dstb;
            if (sel == 0)      { src = Ah + (size_t)(bm + row) * DM + k0; dstb = AH_OFF(buf); }
            else if (sel == 1) { src = Al + (size_t)(bm + row) * DM + k0; dstb = AL_OFF(buf); }
            else               { src = Bh + (size_t)(bn + row) * DM + k0; dstb = BH_OFF(buf); }
            CP_ASYNC16(dstb + SMEM_SWIZZLE_128B((uint32_t)(row * 128 + seg * 16)), src + seg * 8);
        }
        CP_COMMIT();
    };

    load_chunk(0);
    const int lr = lane & 15, kh = lane >> 4;
    const int kc = DM >> 6;

    for (int c = 0; c < kc; c++) {
        if (c + 1 < kc) { load_chunk(c + 1); CP_WAIT1(); }
        else            { CP_WAIT0(); }
        __syncthreads();
        int buf = c & 1;
#pragma unroll
        for (int kk = 0; kk < 4; kk++) {
            uint32_t aH[2][4], aL[2][4];
#pragma unroll
            for (int i = 0; i < 2; i++) {
                uint32_t ra = SMEM_SWIZZLE_128B((uint32_t)((wm + i * 16 + lr) * 128 + kk * 32 + kh * 16));
                ldm_x4(aH[i], AH_OFF(buf) + ra);
                ldm_x4(aL[i], AL_OFF(buf) + ra);
            }
#pragma unroll
            for (int j = 0; j < 4; j++) {
                uint32_t bfr[4];
                ldm_x4(bfr, BH_OFF(buf) +
                       SMEM_SWIZZLE_128B((uint32_t)((wn + j * 16 + lr) * 128 + kk * 32 + kh * 16)));
                uint32_t blo[2] = { bfr[0], bfr[2] };
                uint32_t bhi[2] = { bfr[1], bfr[3] };
#pragma unroll
                for (int i = 0; i < 2; i++) {
                    mma_f16(acc[i][2 * j],     aH[i], blo);
                    mma_f16(acc[i][2 * j + 1], aH[i], bhi);
                    mma_f16(acc[i][2 * j],     aL[i], blo);
                    mma_f16(acc[i][2 * j + 1], aL[i], bhi);
                }
            }
        }
        __syncthreads();
    }

    const int rl = lane >> 2, cl = (lane & 3) * 2;

    if (EPI == 0) {
#pragma unroll
        for (int i = 0; i < 2; i++)
#pragma unroll
            for (int j = 0; j < 8; j++) {
                int row0 = bm + wm + i * 16 + rl;
                int col  = bn + wn + j * 8 + cl;
                float2 lo; lo.x = acc[i][j][0]; lo.y = acc[i][j][1];
                float2 hi; hi.x = acc[i][j][2]; hi.y = acc[i][j][3];
                *(float2*)(Cf + (size_t)row0 * DM + col) = lo;
                *(float2*)(Cf + (size_t)(row0 + 8) * DM + col) = hi;
            }
    } else if (EPI == 2) {
#pragma unroll
        for (int i = 0; i < 2; i++)
#pragma unroll
            for (int j = 0; j < 8; j++) {
                int row0 = bm + wm + i * 16 + rl;
                int col  = bn + wn + j * 8 + cl;
                *(__half2*)(OutH + (size_t)row0 * DM + col) =
                    __floats2half2_rn(acc[i][j][0], acc[i][j][1]);
                *(__half2*)(OutH + (size_t)(row0 + 8) * DM + col) =
                    __floats2half2_rn(acc[i][j][2], acc[i][j][3]);
            }
    } else {
        // EPI 1: RMSNorm + RoPE epilogue. Warp's 64 cols = one full head.
        const int head = (bn >> 6) + (wn >> 6);
        const float postmul = (zb == 0) ? 0.125f : 1.0f;
        const float* sc = (zb == 0) ? qscale : kscale;
        const bool wantLo = (zb == 0);
#pragma unroll
        for (int i = 0; i < 2; i++) {
#pragma unroll
            for (int half = 0; half < 2; half++) {
                int row = bm + wm + i * 16 + rl + half * 8;
                int b = row >> 11, s = row & (SEQ - 1);
                float ss = 0.f;
#pragma unroll
                for (int j = 0; j < 8; j++) {
                    float a0 = acc[i][j][2 * half], a1 = acc[i][j][2 * half + 1];
                    ss += a0 * a0 + a1 * a1;
                }
                ss += __shfl_xor_sync(0xffffffffu, ss, 1);
                ss += __shfl_xor_sync(0xffffffffu, ss, 2);
                float r = rsqrtf(ss * (1.0f / 64.0f) + EPSV);
                int z = b * NH + head;
                size_t rowoff = ((size_t)z * SEQ + s) * HD;
#pragma unroll
                for (int j = 0; j < 8; j++) {
                    int ch = j * 8 + cl;
                    int f = ch >> 1;
                    float c_ = cosT[s * 32 + f];
                    float sn = sinT[s * 32 + f];
                    float tr = acc[i][j][2 * half] * r * sc[ch];
                    float ti = acc[i][j][2 * half + 1] * r * sc[ch + 1];
                    float ox = (tr * c_ - ti * sn) * postmul;
                    float oy = (tr * sn + ti * c_) * postmul;
                    __half2 hp = __floats2half2_rn(ox, oy);
                    if (wantLo) {
                        *(__half2*)(OutH + rowoff + ch) = hp;
                        float2 hf = __half22float2(hp);
                        *(__half2*)(OutL + rowoff + ch) =
                            __floats2half2_rn(ox - hf.x, oy - hf.y);
                    } else {
                        *(__half2*)(OutK + rowoff + ch) = hp;
                    }
                }
            }
        }
    }
}

// ---------------------------------------------------------------------------
// Fused flash attention, fp16 mma, 2-pass split (Q and P corrected; K, V hi).
// Grid: (SEQ/128, NH, BATCH), 256 threads (8 warps, each 16 q-rows).
// ---------------------------------------------------------------------------
__global__ void __launch_bounds__(256, 1) flash_attn(
    const __half* __restrict__ Qh, const __half* __restrict__ Ql,
    const __half* __restrict__ Kh, const __half* __restrict__ Vth,
    __half* __restrict__ Oh, __half* __restrict__ Ol)
{
    extern __shared__ char smem[];
    uint32_t raw = smem_to_u32(smem);
    uint32_t base = (raw + 1023u) & ~1023u;
    const uint32_t QH_OFF = base, QL_OFF = base + 16384u;
    auto KH_OFF = [&](int buf) { return base + 32768u + (uint32_t)buf * 32768u; };
    auto VH_OFF = [&](int buf) { return KH_OFF(buf) + 16384u; };

    const int tid = threadIdx.x;
    const int lane = tid & 31, wid = tid >> 5;
    const int lr = lane & 15, kh4 = lane >> 4;
    const int wm = wid * 16;

    const int z = blockIdx.z * NH + blockIdx.y;
    const int b = blockIdx.z, h = blockIdx.y;
    const int q0 = blockIdx.x * 128;

    const __half* qh = Qh + ((size_t)z * SEQ + q0) * HD;
    const __half* ql = Ql + ((size_t)z * SEQ + q0) * HD;
    const __half* kbh = Kh + (size_t)z * SEQ * HD;
    const __half* vth = Vth + (size_t)z * HD * SEQ;

    for (int idx = tid; idx < 2048; idx += 256) {
        bool isH = idx < 1024;
        int li = idx & 1023;
        int row = li >> 3, seg = li & 7;
        const __half* src = (isH ? qh : ql) + (size_t)row * HD + seg * 8;
        uint32_t dst = (isH ? QH_OFF : QL_OFF) + SMEM_SWIZZLE_128B((uint32_t)(row * 128 + seg * 16));
        CP_ASYNC16(dst, src);
    }

    auto load_tile = [&](int kt, int buf) {
        for (int idx = tid; idx < 1024; idx += 256) {
            int row = idx >> 3, seg = idx & 7;
            CP_ASYNC16(KH_OFF(buf) + SMEM_SWIZZLE_128B((uint32_t)(row * 128 + seg * 16)),
                       kbh + (size_t)(kt + row) * HD + seg * 8);
        }
        for (int idx = tid; idx < 1024; idx += 256) {
            int d = idx >> 4;
            int hk = (idx >> 3) & 1, seg = idx & 7;
            CP_ASYNC16(VH_OFF(buf) + hk * 8192u + SMEM_SWIZZLE_128B((uint32_t)(d * 128 + seg * 16)),
                       vth + (size_t)d * SEQ + kt + hk * 64 + seg * 8);
        }
        CP_COMMIT();
    };

    load_tile(0, 0);

    float m_i[2] = { -INFINITY, -INFINITY };
    float l_i[2] = { 0.f, 0.f };
    float oacc[8][4];
#pragma unroll
    for (int j = 0; j < 8; j++)
#pragma unroll
        for (int q = 0; q < 4; q++) oacc[j][q] = 0.f;

    const int NT = SEQ / 128;
    for (int c = 0; c < NT; c++) {
        int buf = c & 1;
        if (c + 1 < NT) { load_tile((c + 1) * 128, buf ^ 1); CP_WAIT1(); }
        else            { CP_WAIT0(); }
        __syncthreads();

        float sacc[16][4];
#pragma unroll
        for (int j = 0; j < 16; j++)
#pragma unroll
            for (int q = 0; q < 4; q++) sacc[j][q] = 0.f;

#pragma unroll
        for (int kk = 0; kk < 4; kk++) {
            uint32_t ra = SMEM_SWIZZLE_128B((uint32_t)((wm + lr) * 128 + kk * 32 + kh4 * 16));
            uint32_t aH[4], aL[4];
            ldm_x4(aH, QH_OFF + ra);
            ldm_x4(aL, QL_OFF + ra);
#pragma unroll
            for (int nf = 0; nf < 8; nf++) {
                uint32_t bh4[4];
                ldm_x4(bh4, KH_OFF(buf) +
                       SMEM_SWIZZLE_128B((uint32_t)((nf * 16 + lr) * 128 + kk * 32 + kh4 * 16)));
                uint32_t blo[2] = { bh4[0], bh4[2] }, bhi[2] = { bh4[1], bh4[3] };
                mma_f16(sacc[2 * nf],     aH, blo);
                mma_f16(sacc[2 * nf + 1], aH, bhi);
                mma_f16(sacc[2 * nf],     aL, blo);
                mma_f16(sacc[2 * nf + 1], aL, bhi);
            }
        }

        float tmax[2] = { -INFINITY, -INFINITY };
#pragma unroll
        for (int j = 0; j < 16; j++) {
            tmax[0] = fmaxf(tmax[0], fmaxf(sacc[j][0], sacc[j][1]));
            tmax[1] = fmaxf(tmax[1], fmaxf(sacc[j][2], sacc[j][3]));
        }
#pragma unroll
        for (int mk = 1; mk <= 2; mk <<= 1) {
            tmax[0] = fmaxf(tmax[0], __shfl_xor_sync(0xffffffffu, tmax[0], mk));
            tmax[1] = fmaxf(tmax[1], __shfl_xor_sync(0xffffffffu, tmax[1], mk));
        }
        float mnew0 = fmaxf(m_i[0], tmax[0]);
        float mnew1 = fmaxf(m_i[1], tmax[1]);
        float al0 = __expf(m_i[0] - mnew0);
        float al1 = __expf(m_i[1] - mnew1);
        m_i[0] = mnew0; m_i[1] = mnew1;
        float rs0 = 0.f, rs1 = 0.f;
#pragma unroll
        for (int j = 0; j < 16; j++) {
            sacc[j][0] = __expf(sacc[j][0] - mnew0);
            sacc[j][1] = __expf(sacc[j][1] - mnew0);
            sacc[j][2] = __expf(sacc[j][2] - mnew1);
            sacc[j][3] = __expf(sacc[j][3] - mnew1);
            rs0 += sacc[j][0] + sacc[j][1];
            rs1 += sacc[j][2] + sacc[j][3];
        }
#pragma unroll
        for (int mk = 1; mk <= 2; mk <<= 1) {
            rs0 += __shfl_xor_sync(0xffffffffu, rs0, mk);
            rs1 += __shfl_xor_sync(0xffffffffu, rs1, mk);
        }
        l_i[0] = l_i[0] * al0 + rs0;
        l_i[1] = l_i[1] * al1 + rs1;
#pragma unroll
        for (int j = 0; j < 8; j++) {
            oacc[j][0] *= al0; oacc[j][1] *= al0;
            oacc[j][2] *= al1; oacc[j][3] *= al1;
        }

#pragma unroll
        for (int kk = 0; kk < 8; kk++) {
            float p0 = sacc[2 * kk][0],     p1 = sacc[2 * kk][1];
            float p2 = sacc[2 * kk][2],     p3 = sacc[2 * kk][3];
            float p4 = sacc[2 * kk + 1][0], p5 = sacc[2 * kk + 1][1];
            float p6 = sacc[2 * kk + 1][2], p7 = sacc[2 * kk + 1][3];
            __half2 h01 = __floats2half2_rn(p0, p1);
            __half2 h23 = __floats2half2_rn(p2, p3);
            __half2 h45 = __floats2half2_rn(p4, p5);
            __half2 h67 = __floats2half2_rn(p6, p7);
            uint32_t ah[4] = { h2u(h01), h2u(h23), h2u(h45), h2u(h67) };
            float2 f01 = __half22float2(h01);
            float2 f23 = __half22float2(h23);
            float2 f45 = __half22float2(h45);
            float2 f67 = __half22float2(h67);
            uint32_t alr[4] = {
                h2u(__floats2half2_rn(p0 - f01.x, p1 - f01.y)),
                h2u(__floats2half2_rn(p2 - f23.x, p3 - f23.y)),
                h2u(__floats2half2_rn(p4 - f45.x, p5 - f45.y)),
                h2u(__floats2half2_rn(p6 - f67.x, p7 - f67.y))
            };
            int hk = kk >> 2, kv = kk & 3;
#pragma unroll
            for (int nfp = 0; nfp < 4; nfp++) {
                uint32_t bh4[4];
                ldm_x4(bh4, VH_OFF(buf) + hk * 8192u +
                       SMEM_SWIZZLE_128B((uint32_t)((nfp * 16 + lr) * 128 + kv * 32 + kh4 * 16)));
                uint32_t blo[2] = { bh4[0], bh4[2] }, bhi[2] = { bh4[1], bh4[3] };
                mma_f16(oacc[2 * nfp],     ah, blo);
                mma_f16(oacc[2 * nfp + 1], ah, bhi);
                mma_f16(oacc[2 * nfp],     alr, blo);
                mma_f16(oacc[2 * nfp + 1], alr, bhi);
            }
        }
        __syncthreads();
    }

    float inv0 = 1.0f / l_i[0], inv1 = 1.0f / l_i[1];
    int row0 = q0 + wm + (lane >> 2);
    int colb = h * HD + (lane & 3) * 2;
#pragma unroll
    for (int j = 0; j < 8; j++) {
        float x0 = oacc[j][0] * inv0, x1 = oacc[j][1] * inv0;
        float x2 = oacc[j][2] * inv1, x3 = oacc[j][3] * inv1;
        size_t off0 = ((size_t)(b * SEQ + row0)) * DM + colb + j * 8;
        size_t off1 = ((size_t)(b * SEQ + row0 + 8)) * DM + colb + j * 8;
        __half2 hp0 = __floats2half2_rn(x0, x1);
        __half2 hp1 = __floats2half2_rn(x2, x3);
        *(__half2*)(Oh + off0) = hp0;
        *(__half2*)(Oh + off1) = hp1;
        float2 f0 = __half22float2(hp0);
        float2 f1 = __half22float2(hp1);
        *(__half2*)(Ol + off0) = __floats2half2_rn(x0 - f0.x, x1 - f0.y);
        *(__half2*)(Ol + off1) = __floats2half2_rn(x2 - f1.x, x3 - f1.y);
    }
}

// ---------------------------------------------------------------------------
extern "C" void kernel_launch(void* const* d_in, const int* in_sizes, int n_in,
                              void* d_out, int out_size)
{
    const float* x        = (const float*)d_in[0];
    const float* wq       = (const float*)d_in[1];
    const float* wk       = (const float*)d_in[2];
    const float* wv       = (const float*)d_in[3];
    const float* wo       = (const float*)d_in[4];
    const float* q_scale  = (const float*)d_in[5];
    const float* k_scale  = (const float*)d_in[6];
    const float* rope_cos = (const float*)d_in[7];
    const float* rope_sin = (const float*)d_in[8];
    float* out = (float*)d_out;

    __half *xh, *xl, *wqh, *wkh, *wvh, *woh;
    __half *qbh, *qbl, *kbh, *vh16, *vth, *ath, *atl;
    cudaGetSymbolAddress((void**)&xh, g_xh);     cudaGetSymbolAddress((void**)&xl, g_xl);
    cudaGetSymbolAddress((void**)&wqh, g_wqh);   cudaGetSymbolAddress((void**)&wkh, g_wkh);
    cudaGetSymbolAddress((void**)&wvh, g_wvh);   cudaGetSymbolAddress((void**)&woh, g_woh);
    cudaGetSymbolAddress((void**)&qbh, g_qbh);   cudaGetSymbolAddress((void**)&qbl, g_qbl);
    cudaGetSymbolAddress((void**)&kbh, g_kbh);
    cudaGetSymbolAddress((void**)&vh16, g_vh16); cudaGetSymbolAddress((void**)&vth, g_vth);
    cudaGetSymbolAddress((void**)&ath, g_ath);   cudaGetSymbolAddress((void**)&atl, g_atl);

    const int SMG = 1024 + 2 * 49152;
    const int SMF = 1024 + 32768 + 2 * 32768;
    cudaFuncSetAttribute(proj_mm<0>, cudaFuncAttributeMaxDynamicSharedMemorySize, SMG);
    cudaFuncSetAttribute(proj_mm<1>, cudaFuncAttributeMaxDynamicSharedMemorySize, SMG);
    cudaFuncSetAttribute(proj_mm<2>, cudaFuncAttributeMaxDynamicSharedMemorySize, SMG);
    cudaFuncSetAttribute(flash_attn, cudaFuncAttributeMaxDynamicSharedMemorySize, SMF);

    const int NXE = BATCH * SEQ * DM;
    const int NWE = DM * DM;

    split_f32h<<<(NXE + 255) / 256, 256>>>(x, xh, xl, NXE);
    conv_weights<<<(4 * NWE) / 256, 256>>>(wq, wk, wv, wo, wqh, wkh, wvh, woh);

    dim3 pg(DM / 128, (BATCH * SEQ) / 128);
    // Q + K projections fused with RMSNorm + RoPE (z = 0 -> Q, z = 1 -> K)
    proj_mm<1><<<dim3(DM / 128, (BATCH * SEQ) / 128, 2), 256, SMG>>>(
        xh, xl, wqh, wkh, nullptr, qbh, qbl, kbh,
        q_scale, k_scale, rope_cos, rope_sin);
    // V projection -> fp16 [b,s,h,d]
    proj_mm<2><<<pg, 256, SMG>>>(
        xh, xl, wvh, nullptr, nullptr, vh16, nullptr, nullptr,
        nullptr, nullptr, nullptr, nullptr);

    vt_h16<<<dim3(SEQ / 32, HD / 32, BATCH * NH), dim3(32, 8)>>>(vh16, vth);

    flash_attn<<<dim3(SEQ / 128, NH, BATCH), 256, SMF>>>(qbh, qbl, kbh, vth, ath, atl);

    // Final projection -> fp32 out
    proj_mm<0><<<pg, 256, SMG>>>(
        ath, atl, woh, nullptr, out, nullptr, nullptr, nullptr,
        nullptr, nullptr, nullptr, nullptr);
}

// round 8
// speedup vs baseline: 5.2787x; 1.0606x over previous
#include <cuda_runtime.h>
#include <cuda_fp16.h>
#include <cstdint>
#include <math.h>

#define BATCH 2
#define SEQ 2048
#define DM 1024
#define NH 16
#define HD 64
#define EPSV 1e-6f

// ---------------------------------------------------------------------------
// Scratch (__device__ globals: allocation-free rule)
// ---------------------------------------------------------------------------
__device__ __half g_xh[BATCH * SEQ * DM];
__device__ __half g_xl[BATCH * SEQ * DM];
__device__ __half g_wqh[DM * DM], g_wkh[DM * DM], g_wvh[DM * DM], g_woh[DM * DM];
__device__ __half g_qbh[BATCH * NH * SEQ * HD], g_qbl[BATCH * NH * SEQ * HD];
__device__ __half g_kbh[BATCH * NH * SEQ * HD];
__device__ __half g_vth[BATCH * NH * HD * SEQ];      // [b,h,d,s] fp16
__device__ __half g_ath[BATCH * SEQ * DM], g_atl[BATCH * SEQ * DM];

// ---------------------------------------------------------------------------
// Helpers (non-'a' instructions only: legal under compute_103)
// ---------------------------------------------------------------------------
__device__ __forceinline__ uint32_t smem_to_u32(const void* p) {
    uint32_t a;
    asm("{ .reg .u64 t; cvta.to.shared.u64 t, %1; cvt.u32.u64 %0, t; }" : "=r"(a) : "l"(p));
    return a;
}
#define SMEM_SWIZZLE_128B(o) ((o) ^ (((o) >> 3) & 0x70))

#define CP_ASYNC16(dst, src) \
    asm volatile("cp.async.cg.shared.global [%0], [%1], 16;" :: "r"(dst), "l"(src))
#define CP_COMMIT() asm volatile("cp.async.commit_group;" ::: "memory")
#define CP_WAIT0()  asm volatile("cp.async.wait_group 0;" ::: "memory")
#define CP_WAIT1()  asm volatile("cp.async.wait_group 1;" ::: "memory")

__device__ __forceinline__ void ldm_x4(uint32_t* r, uint32_t addr) {
    asm volatile("ldmatrix.sync.aligned.m8n8.x4.shared.b16 {%0,%1,%2,%3}, [%4];"
                 : "=r"(r[0]), "=r"(r[1]), "=r"(r[2]), "=r"(r[3]) : "r"(addr));
}
__device__ __forceinline__ void mma_f16(float* d, const uint32_t* a, const uint32_t* b) {
    asm volatile("mma.sync.aligned.m16n8k16.row.col.f32.f16.f16.f32 "
        "{%0,%1,%2,%3}, {%4,%5,%6,%7}, {%8,%9}, {%0,%1,%2,%3};"
        : "+f"(d[0]), "+f"(d[1]), "+f"(d[2]), "+f"(d[3])
        : "r"(a[0]), "r"(a[1]), "r"(a[2]), "r"(a[3]), "r"(b[0]), "r"(b[1]));
}
__device__ __forceinline__ uint32_t h2u(__half2 h) { return *reinterpret_cast<uint32_t*>(&h); }

// ---------------------------------------------------------------------------
__global__ void split_f32h(const float* __restrict__ in, __half* __restrict__ h,
                           __half* __restrict__ l, int n)
{
    int i = blockIdx.x * blockDim.x + threadIdx.x;
    if (i < n) {
        float x = in[i];
        __half hi = __float2half_rn(x);
        h[i] = hi;
        l[i] = __float2half_rn(x - __half2float(hi));
    }
}

__global__ void conv_weights(const float* __restrict__ wq, const float* __restrict__ wk,
                             const float* __restrict__ wv, const float* __restrict__ wo,
                             __half* __restrict__ oq, __half* __restrict__ ok,
                             __half* __restrict__ ov, __half* __restrict__ oo)
{
    int i = blockIdx.x * blockDim.x + threadIdx.x;
    int sel = i >> 20, li = i & ((1 << 20) - 1);
    const float* src = sel == 0 ? wq : sel == 1 ? wk : sel == 2 ? wv : wo;
    __half* dst = sel == 0 ? oq : sel == 1 ? ok : sel == 2 ? ov : oo;
    dst[li] = __float2half_rn(src[li]);
}

// ---------------------------------------------------------------------------
// Shared GEMM mainloop: 128x128 tile, BK=64, 2-pass split A(hi+lo) x B(hi).
// acc[i][j][q]: warp tile 32x64 (4m x 2n warps).
// ---------------------------------------------------------------------------
#define GEMM_MAINLOOP(Ahp, Alp, Bhp)                                                   \
    auto AH_OFF = [&](int buf) { return base + (uint32_t)buf * 49152u; };              \
    auto AL_OFF = [&](int buf) { return AH_OFF(buf) + 16384u; };                       \
    auto BH_OFF = [&](int buf) { return AH_OFF(buf) + 32768u; };                       \
    float acc[2][8][4];                                                                \
    _Pragma("unroll") for (int i = 0; i < 2; i++)                                      \
        _Pragma("unroll") for (int j = 0; j < 8; j++)                                  \
            _Pragma("unroll") for (int q = 0; q < 4; q++) acc[i][j][q] = 0.f;          \
    auto load_chunk = [&](int c) {                                                     \
        int k0 = c << 6;                                                               \
        int buf = c & 1;                                                               \
        for (int idx = tid; idx < 3072; idx += 256) {                                  \
            int sel = idx >> 10;                                                       \
            int li = idx & 1023;                                                       \
            int row = li >> 3, seg = li & 7;                                           \
            const __half* src;                                                         \
            uint32_t dstb;                                                             \
            if (sel == 0)      { src = Ahp + (size_t)(bm + row) * DM + k0; dstb = AH_OFF(buf); } \
            else if (sel == 1) { src = Alp + (size_t)(bm + row) * DM + k0; dstb = AL_OFF(buf); } \
            else               { src = Bhp + (size_t)(bn + row) * DM + k0; dstb = BH_OFF(buf); } \
            CP_ASYNC16(dstb + SMEM_SWIZZLE_128B((uint32_t)(row * 128 + seg * 16)), src + seg * 8); \
        }                                                                              \
        CP_COMMIT();                                                                   \
    };                                                                                 \
    load_chunk(0);                                                                     \
    const int lr = lane & 15, kh = lane >> 4;                                          \
    const int kc = DM >> 6;                                                            \
    for (int c = 0; c < kc; c++) {                                                     \
        if (c + 1 < kc) { load_chunk(c + 1); CP_WAIT1(); }                             \
        else            { CP_WAIT0(); }                                                \
        __syncthreads();                                                               \
        int buf = c & 1;                                                               \
        _Pragma("unroll") for (int kk = 0; kk < 4; kk++) {                             \
            uint32_t aH[2][4], aL[2][4];                                               \
            _Pragma("unroll") for (int i = 0; i < 2; i++) {                            \
                uint32_t ra = SMEM_SWIZZLE_128B((uint32_t)((wm + i * 16 + lr) * 128 + kk * 32 + kh * 16)); \
                ldm_x4(aH[i], AH_OFF(buf) + ra);                                       \
                ldm_x4(aL[i], AL_OFF(buf) + ra);                                       \
            }                                                                          \
            _Pragma("unroll") for (int j = 0; j < 4; j++) {                            \
                uint32_t bfr[4];                                                       \
                ldm_x4(bfr, BH_OFF(buf) +                                              \
                       SMEM_SWIZZLE_128B((uint32_t)((wn + j * 16 + lr) * 128 + kk * 32 + kh * 16))); \
                uint32_t blo[2] = { bfr[0], bfr[2] };                                  \
                uint32_t bhi[2] = { bfr[1], bfr[3] };                                  \
                _Pragma("unroll") for (int i = 0; i < 2; i++) {                        \
                    mma_f16(acc[i][2 * j],     aH[i], blo);                            \
                    mma_f16(acc[i][2 * j + 1], aH[i], bhi);                            \
                    mma_f16(acc[i][2 * j],     aL[i], blo);                            \
                    mma_f16(acc[i][2 * j + 1], aL[i], bhi);                            \
                }                                                                      \
            }                                                                          \
        }                                                                              \
        __syncthreads();                                                               \
    }

// ---------------------------------------------------------------------------
// Fused Q/K/V projection. blockIdx.z: 0=Q (norm+rope, hi+lo), 1=K (norm+rope, hi),
// 2=V (transposed fp16 [b,h,d,s] via smem staging).
// ---------------------------------------------------------------------------
__global__ void __launch_bounds__(256, 2) proj_qkv(
    const __half* __restrict__ Ah, const __half* __restrict__ Al,
    const __half* __restrict__ Wq, const __half* __restrict__ Wk, const __half* __restrict__ Wv,
    __half* __restrict__ QbH, __half* __restrict__ QbL, __half* __restrict__ KbH,
    __half* __restrict__ Vt,
    const float* __restrict__ qscale, const float* __restrict__ kscale,
    const float* __restrict__ cosT, const float* __restrict__ sinT)
{
    extern __shared__ char smem[];
    uint32_t raw = smem_to_u32(smem);
    uint32_t base = (raw + 1023u) & ~1023u;

    const int tid = threadIdx.x;
    const int lane = tid & 31, wid = tid >> 5;
    const int wm = (wid >> 1) * 32;
    const int wn = (wid & 1) * 64;
    const int bm = blockIdx.y * 128;
    const int bn = blockIdx.x * 128;
    const int zb = blockIdx.z;
    const __half* Bh = (zb == 0) ? Wq : (zb == 1) ? Wk : Wv;

    GEMM_MAINLOOP(Ah, Al, Bh)

    const int rl = lane >> 2, cl = (lane & 3) * 2;

    if (zb == 2) {
        // ---- V: stage [col][row] fp16 in smem, write [b,h,d,s] with 16B stores
        __half* st = reinterpret_cast<__half*>(smem + (base - raw));
#pragma unroll
        for (int i = 0; i < 2; i++)
#pragma unroll
            for (int j = 0; j < 8; j++) {
                int row0 = wm + i * 16 + rl;
                int col  = wn + j * 8 + cl;
                st[(col)     * 136 + row0]     = __float2half_rn(acc[i][j][0]);
                st[(col + 1) * 136 + row0]     = __float2half_rn(acc[i][j][1]);
                st[(col)     * 136 + row0 + 8] = __float2half_rn(acc[i][j][2]);
                st[(col + 1) * 136 + row0 + 8] = __float2half_rn(acc[i][j][3]);
            }
        __syncthreads();
        int b = bm >> 11, s0 = bm & (SEQ - 1);
        int hbase = bn >> 6;
        for (int t = tid; t < 2048; t += 256) {
            int col = t >> 4, sc = t & 15;
            uint4 v = *reinterpret_cast<uint4*>(&st[col * 136 + sc * 8]);
            int head = hbase + (col >> 6), d = col & 63;
            *reinterpret_cast<uint4*>(
                Vt + ((size_t)(b * NH + head) * HD + d) * SEQ + s0 + sc * 8) = v;
        }
    } else {
        // ---- Q/K: RMSNorm + RoPE epilogue. Warp's 64 cols = one full head.
        const int head = (bn >> 6) + (wn >> 6);
        const float postmul = (zb == 0) ? 0.125f : 1.0f;
        const float* sc = (zb == 0) ? qscale : kscale;
        const bool wantLo = (zb == 0);
#pragma unroll
        for (int i = 0; i < 2; i++) {
#pragma unroll
            for (int half = 0; half < 2; half++) {
                int row = bm + wm + i * 16 + rl + half * 8;
                int b = row >> 11, s = row & (SEQ - 1);
                float ss = 0.f;
#pragma unroll
                for (int j = 0; j < 8; j++) {
                    float a0 = acc[i][j][2 * half], a1 = acc[i][j][2 * half + 1];
                    ss += a0 * a0 + a1 * a1;
                }
                ss += __shfl_xor_sync(0xffffffffu, ss, 1);
                ss += __shfl_xor_sync(0xffffffffu, ss, 2);
                float r = rsqrtf(ss * (1.0f / 64.0f) + EPSV);
                int z = b * NH + head;
                size_t rowoff = ((size_t)z * SEQ + s) * HD;
#pragma unroll
                for (int j = 0; j < 8; j++) {
                    int ch = j * 8 + cl;
                    int f = ch >> 1;
                    float c_ = cosT[s * 32 + f];
                    float sn = sinT[s * 32 + f];
                    float tr = acc[i][j][2 * half] * r * sc[ch];
                    float ti = acc[i][j][2 * half + 1] * r * sc[ch + 1];
                    float ox = (tr * c_ - ti * sn) * postmul;
                    float oy = (tr * sn + ti * c_) * postmul;
                    __half2 hp = __floats2half2_rn(ox, oy);
                    if (wantLo) {
                        *(__half2*)(QbH + rowoff + ch) = hp;
                        float2 hf = __half22float2(hp);
                        *(__half2*)(QbL + rowoff + ch) =
                            __floats2half2_rn(ox - hf.x, oy - hf.y);
                    } else {
                        *(__half2*)(KbH + rowoff + ch) = hp;
                    }
                }
            }
        }
    }
}

// ---------------------------------------------------------------------------
// Output projection: attn(split fp16) x Wo(hi) -> fp32 out
// ---------------------------------------------------------------------------
__global__ void __launch_bounds__(256, 2) proj_out(
    const __half* __restrict__ Ah, const __half* __restrict__ Al,
    const __half* __restrict__ Bhw, float* __restrict__ Cf)
{
    extern __shared__ char smem[];
    uint32_t raw = smem_to_u32(smem);
    uint32_t base = (raw + 1023u) & ~1023u;

    const int tid = threadIdx.x;
    const int lane = tid & 31, wid = tid >> 5;
    const int wm = (wid >> 1) * 32;
    const int wn = (wid & 1) * 64;
    const int bm = blockIdx.y * 128;
    const int bn = blockIdx.x * 128;

    GEMM_MAINLOOP(Ah, Al, Bhw)

    const int rl = lane >> 2, cl = (lane & 3) * 2;
#pragma unroll
    for (int i = 0; i < 2; i++)
#pragma unroll
        for (int j = 0; j < 8; j++) {
            int row0 = bm + wm + i * 16 + rl;
            int col  = bn + wn + j * 8 + cl;
            float2 lo; lo.x = acc[i][j][0]; lo.y = acc[i][j][1];
            float2 hi; hi.x = acc[i][j][2]; hi.y = acc[i][j][3];
            *(float2*)(Cf + (size_t)row0 * DM + col) = lo;
            *(float2*)(Cf + (size_t)(row0 + 8) * DM + col) = hi;
        }
}

// ---------------------------------------------------------------------------
// Fused flash attention, fp16 mma, 2-pass split (Q and P corrected; K, V hi).
// Grid: (SEQ/128, NH, BATCH), 256 threads (8 warps, each 16 q-rows).
// ---------------------------------------------------------------------------
__global__ void __launch_bounds__(256, 1) flash_attn(
    const __half* __restrict__ Qh, const __half* __restrict__ Ql,
    const __half* __restrict__ Kh, const __half* __restrict__ Vth,
    __half* __restrict__ Oh, __half* __restrict__ Ol)
{
    extern __shared__ char smem[];
    uint32_t raw = smem_to_u32(smem);
    uint32_t base = (raw + 1023u) & ~1023u;
    const uint32_t QH_OFF = base, QL_OFF = base + 16384u;
    auto KH_OFF = [&](int buf) { return base + 32768u + (uint32_t)buf * 32768u; };
    auto VH_OFF = [&](int buf) { return KH_OFF(buf) + 16384u; };

    const int tid = threadIdx.x;
    const int lane = tid & 31, wid = tid >> 5;
    const int lr = lane & 15, kh4 = lane >> 4;
    const int wm = wid * 16;

    const int z = blockIdx.z * NH + blockIdx.y;
    const int b = blockIdx.z, h = blockIdx.y;
    const int q0 = blockIdx.x * 128;

    const __half* qh = Qh + ((size_t)z * SEQ + q0) * HD;
    const __half* ql = Ql + ((size_t)z * SEQ + q0) * HD;
    const __half* kbh = Kh + (size_t)z * SEQ * HD;
    const __half* vth = Vth + (size_t)z * HD * SEQ;

    for (int idx = tid; idx < 2048; idx += 256) {
        bool isH = idx < 1024;
        int li = idx & 1023;
        int row = li >> 3, seg = li & 7;
        const __half* src = (isH ? qh : ql) + (size_t)row * HD + seg * 8;
        uint32_t dst = (isH ? QH_OFF : QL_OFF) + SMEM_SWIZZLE_128B((uint32_t)(row * 128 + seg * 16));
        CP_ASYNC16(dst, src);
    }

    auto load_tile = [&](int kt, int buf) {
        for (int idx = tid; idx < 1024; idx += 256) {
            int row = idx >> 3, seg = idx & 7;
            CP_ASYNC16(KH_OFF(buf) + SMEM_SWIZZLE_128B((uint32_t)(row * 128 + seg * 16)),
                       kbh + (size_t)(kt + row) * HD + seg * 8);
        }
        for (int idx = tid; idx < 1024; idx += 256) {
            int d = idx >> 4;
            int hk = (idx >> 3) & 1, seg = idx & 7;
            CP_ASYNC16(VH_OFF(buf) + hk * 8192u + SMEM_SWIZZLE_128B((uint32_t)(d * 128 + seg * 16)),
                       vth + (size_t)d * SEQ + kt + hk * 64 + seg * 8);
        }
        CP_COMMIT();
    };

    load_tile(0, 0);

    float m_i[2] = { -INFINITY, -INFINITY };
    float l_i[2] = { 0.f, 0.f };
    float oacc[8][4];
#pragma unroll
    for (int j = 0; j < 8; j++)
#pragma unroll
        for (int q = 0; q < 4; q++) oacc[j][q] = 0.f;

    const int NT = SEQ / 128;
    for (int c = 0; c < NT; c++) {
        int buf = c & 1;
        if (c + 1 < NT) { load_tile((c + 1) * 128, buf ^ 1); CP_WAIT1(); }
        else            { CP_WAIT0(); }
        __syncthreads();

        float sacc[16][4];
#pragma unroll
        for (int j = 0; j < 16; j++)
#pragma unroll
            for (int q = 0; q < 4; q++) sacc[j][q] = 0.f;

#pragma unroll
        for (int kk = 0; kk < 4; kk++) {
            uint32_t ra = SMEM_SWIZZLE_128B((uint32_t)((wm + lr) * 128 + kk * 32 + kh4 * 16));
            uint32_t aH[4], aL[4];
            ldm_x4(aH, QH_OFF + ra);
            ldm_x4(aL, QL_OFF + ra);
#pragma unroll
            for (int nf = 0; nf < 8; nf++) {
                uint32_t bh4[4];
                ldm_x4(bh4, KH_OFF(buf) +
                       SMEM_SWIZZLE_128B((uint32_t)((nf * 16 + lr) * 128 + kk * 32 + kh4 * 16)));
                uint32_t blo[2] = { bh4[0], bh4[2] }, bhi[2] = { bh4[1], bh4[3] };
                mma_f16(sacc[2 * nf],     aH, blo);
                mma_f16(sacc[2 * nf + 1], aH, bhi);
                mma_f16(sacc[2 * nf],     aL, blo);
                mma_f16(sacc[2 * nf + 1], aL, bhi);
            }
        }

        float tmax[2] = { -INFINITY, -INFINITY };
#pragma unroll
        for (int j = 0; j < 16; j++) {
            tmax[0] = fmaxf(tmax[0], fmaxf(sacc[j][0], sacc[j][1]));
            tmax[1] = fmaxf(tmax[1], fmaxf(sacc[j][2], sacc[j][3]));
        }
#pragma unroll
        for (int mk = 1; mk <= 2; mk <<= 1) {
            tmax[0] = fmaxf(tmax[0], __shfl_xor_sync(0xffffffffu, tmax[0], mk));
            tmax[1] = fmaxf(tmax[1], __shfl_xor_sync(0xffffffffu, tmax[1], mk));
        }
        float mnew0 = fmaxf(m_i[0], tmax[0]);
        float mnew1 = fmaxf(m_i[1], tmax[1]);
        float al0 = __expf(m_i[0] - mnew0);
        float al1 = __expf(m_i[1] - mnew1);
        m_i[0] = mnew0; m_i[1] = mnew1;
        float rs0 = 0.f, rs1 = 0.f;
#pragma unroll
        for (int j = 0; j < 16; j++) {
            sacc[j][0] = __expf(sacc[j][0] - mnew0);
            sacc[j][1] = __expf(sacc[j][1] - mnew0);
            sacc[j][2] = __expf(sacc[j][2] - mnew1);
            sacc[j][3] = __expf(sacc[j][3] - mnew1);
            rs0 += sacc[j][0] + sacc[j][1];
            rs1 += sacc[j][2] + sacc[j][3];
        }
#pragma unroll
        for (int mk = 1; mk <= 2; mk <<= 1) {
            rs0 += __shfl_xor_sync(0xffffffffu, rs0, mk);
            rs1 += __shfl_xor_sync(0xffffffffu, rs1, mk);
        }
        l_i[0] = l_i[0] * al0 + rs0;
        l_i[1] = l_i[1] * al1 + rs1;
#pragma unroll
        for (int j = 0; j < 8; j++) {
            oacc[j][0] *= al0; oacc[j][1] *= al0;
            oacc[j][2] *= al1; oacc[j][3] *= al1;
        }

#pragma unroll
        for (int kk = 0; kk < 8; kk++) {
            float p0 = sacc[2 * kk][0],     p1 = sacc[2 * kk][1];
            float p2 = sacc[2 * kk][2],     p3 = sacc[2 * kk][3];
            float p4 = sacc[2 * kk + 1][0], p5 = sacc[2 * kk + 1][1];
            float p6 = sacc[2 * kk + 1][2], p7 = sacc[2 * kk + 1][3];
            __half2 h01 = __floats2half2_rn(p0, p1);
            __half2 h23 = __floats2half2_rn(p2, p3);
            __half2 h45 = __floats2half2_rn(p4, p5);
            __half2 h67 = __floats2half2_rn(p6, p7);
            uint32_t ah[4] = { h2u(h01), h2u(h23), h2u(h45), h2u(h67) };
            float2 f01 = __half22float2(h01);
            float2 f23 = __half22float2(h23);
            float2 f45 = __half22float2(h45);
            float2 f67 = __half22float2(h67);
            uint32_t alr[4] = {
                h2u(__floats2half2_rn(p0 - f01.x, p1 - f01.y)),
                h2u(__floats2half2_rn(p2 - f23.x, p3 - f23.y)),
                h2u(__floats2half2_rn(p4 - f45.x, p5 - f45.y)),
                h2u(__floats2half2_rn(p6 - f67.x, p7 - f67.y))
            };
            int hk = kk >> 2, kv = kk & 3;
#pragma unroll
            for (int nfp = 0; nfp < 4; nfp++) {
                uint32_t bh4[4];
                ldm_x4(bh4, VH_OFF(buf) + hk * 8192u +
                       SMEM_SWIZZLE_128B((uint32_t)((nfp * 16 + lr) * 128 + kv * 32 + kh4 * 16)));
                uint32_t blo[2] = { bh4[0], bh4[2] }, bhi[2] = { bh4[1], bh4[3] };
                mma_f16(oacc[2 * nfp],     ah, blo);
                mma_f16(oacc[2 * nfp + 1], ah, bhi);
                mma_f16(oacc[2 * nfp],     alr, blo);
                mma_f16(oacc[2 * nfp + 1], alr, bhi);
            }
        }
        __syncthreads();
    }

    float inv0 = 1.0f / l_i[0], inv1 = 1.0f / l_i[1];
    int row0 = q0 + wm + (lane >> 2);
    int colb = h * HD + (lane & 3) * 2;
#pragma unroll
    for (int j = 0; j < 8; j++) {
        float x0 = oacc[j][0] * inv0, x1 = oacc[j][1] * inv0;
        float x2 = oacc[j][2] * inv1, x3 = oacc[j][3] * inv1;
        size_t off0 = ((size_t)(b * SEQ + row0)) * DM + colb + j * 8;
        size_t off1 = ((size_t)(b * SEQ + row0 + 8)) * DM + colb + j * 8;
        __half2 hp0 = __floats2half2_rn(x0, x1);
        __half2 hp1 = __floats2half2_rn(x2, x3);
        *(__half2*)(Oh + off0) = hp0;
        *(__half2*)(Oh + off1) = hp1;
        float2 f0 = __half22float2(hp0);
        float2 f1 = __half22float2(hp1);
        *(__half2*)(Ol + off0) = __floats2half2_rn(x0 - f0.x, x1 - f0.y);
        *(__half2*)(Ol + off1) = __floats2half2_rn(x2 - f1.x, x3 - f1.y);
    }
}

// ---------------------------------------------------------------------------
extern "C" void kernel_launch(void* const* d_in, const int* in_sizes, int n_in,
                              void* d_out, int out_size)
{
    const float* x        = (const float*)d_in[0];
    const float* wq       = (const float*)d_in[1];
    const float* wk       = (const float*)d_in[2];
    const float* wv       = (const float*)d_in[3];
    const float* wo       = (const float*)d_in[4];
    const float* q_scale  = (const float*)d_in[5];
    const float* k_scale  = (const float*)d_in[6];
    const float* rope_cos = (const float*)d_in[7];
    const float* rope_sin = (const float*)d_in[8];
    float* out = (float*)d_out;

    __half *xh, *xl, *wqh, *wkh, *wvh, *woh;
    __half *qbh, *qbl, *kbh, *vth, *ath, *atl;
    cudaGetSymbolAddress((void**)&xh, g_xh);     cudaGetSymbolAddress((void**)&xl, g_xl);
    cudaGetSymbolAddress((void**)&wqh, g_wqh);   cudaGetSymbolAddress((void**)&wkh, g_wkh);
    cudaGetSymbolAddress((void**)&wvh, g_wvh);   cudaGetSymbolAddress((void**)&woh, g_woh);
    cudaGetSymbolAddress((void**)&qbh, g_qbh);   cudaGetSymbolAddress((void**)&qbl, g_qbl);
    cudaGetSymbolAddress((void**)&kbh, g_kbh);
    cudaGetSymbolAddress((void**)&vth, g_vth);
    cudaGetSymbolAddress((void**)&ath, g_ath);   cudaGetSymbolAddress((void**)&atl, g_atl);

    const int SMG = 1024 + 2 * 49152;
    const int SMF = 1024 + 32768 + 2 * 32768;
    cudaFuncSetAttribute(proj_qkv, cudaFuncAttributeMaxDynamicSharedMemorySize, SMG);
    cudaFuncSetAttribute(proj_out, cudaFuncAttributeMaxDynamicSharedMemorySize, SMG);
    cudaFuncSetAttribute(flash_attn, cudaFuncAttributeMaxDynamicSharedMemorySize, SMF);

    const int NXE = BATCH * SEQ * DM;
    const int NWE = DM * DM;

    split_f32h<<<(NXE + 255) / 256, 256>>>(x, xh, xl, NXE);
    conv_weights<<<(4 * NWE) / 256, 256>>>(wq, wk, wv, wo, wqh, wkh, wvh, woh);

    // Q/K/V projections in one launch (z = 0:Q, 1:K, 2:V-transposed)
    proj_qkv<<<dim3(DM / 128, (BATCH * SEQ) / 128, 3), 256, SMG>>>(
        xh, xl, wqh, wkh, wvh, qbh, qbl, kbh, vth,
        q_scale, k_scale, rope_cos, rope_sin);

    flash_attn<<<dim3(SEQ / 128, NH, BATCH), 256, SMF>>>(qbh, qbl, kbh, vth, ath, atl);

    proj_out<<<dim3(DM / 128, (BATCH * SEQ) / 128), 256, SMG>>>(ath, atl, woh, out);
}